// round 1
// baseline (speedup 1.0000x reference)
#include <cuda_runtime.h>
#include <math.h>

#define B 32
#define T 32
#define IDIM 8192
#define H 8192
#define ODIM 2048
#define NNZ_HH 1048576
#define NNZ_IH 524288
#define NNZ_HO 262144

// ---------------- device scratch (static, no runtime alloc) ----------------
__device__ float g_xT[(size_t)T * IDIM * B];   // (t, i, b)   32 MB
__device__ float g_pre[(size_t)T * H * B];     // ih@x_t      32 MB
__device__ float g_h[2][H * B];                // ping-pong hidden, 2 MB
__device__ int   g_cnt[H];                     // histogram / fill counters

__device__ int   g_hh_ptr[H + 1];
__device__ int   g_hh_col[NNZ_HH];
__device__ float g_hh_val[NNZ_HH];
__device__ int   g_ih_ptr[H + 1];
__device__ int   g_ih_col[NNZ_IH];
__device__ float g_ih_val[NNZ_IH];
__device__ int   g_ho_ptr[ODIM + 1];
__device__ int   g_ho_col[NNZ_HO];
__device__ float g_ho_val[NNZ_HO];

// ---------------- CSR build ----------------
__global__ void zero_cnt_kernel() {
    int i = blockIdx.x * blockDim.x + threadIdx.x;
    if (i < H) g_cnt[i] = 0;
}

__global__ void zero_h_kernel() {
    int i = blockIdx.x * blockDim.x + threadIdx.x;
    if (i < H * B) g_h[0][i] = 0.0f;
}

__global__ void hist_kernel(const int* __restrict__ rows, int nnz) {
    int i = blockIdx.x * blockDim.x + threadIdx.x;
    if (i < nnz) atomicAdd(&g_cnt[rows[i]], 1);
}

// single-block exclusive scan of g_cnt[0..n) into selected ptr array (+ total at [n])
__global__ void scan_kernel(int which, int n) {
    __shared__ int s[1024];
    int* ptr = (which == 0) ? g_hh_ptr : (which == 1) ? g_ih_ptr : g_ho_ptr;
    int tid = threadIdx.x;
    int per = (n + 1023) >> 10;   // <= 8
    int base = tid * per;
    int local[8];
    int sum = 0;
    for (int j = 0; j < per; j++) {
        int v = (base + j < n) ? g_cnt[base + j] : 0;
        local[j] = sum;
        sum += v;
    }
    s[tid] = sum;
    __syncthreads();
    for (int off = 1; off < 1024; off <<= 1) {
        int v = (tid >= off) ? s[tid - off] : 0;
        __syncthreads();
        s[tid] += v;
        __syncthreads();
    }
    int excl = tid ? s[tid - 1] : 0;
    for (int j = 0; j < per; j++)
        if (base + j < n) ptr[base + j] = excl + local[j];
    if (tid == 1023) ptr[n] = s[1023];
}

__global__ void scatter_kernel(const int* __restrict__ rows,
                               const int* __restrict__ cols,
                               const float* __restrict__ vals,
                               int which, int nnz) {
    const int* ptr = (which == 0) ? g_hh_ptr : (which == 1) ? g_ih_ptr : g_ho_ptr;
    int*   ocol = (which == 0) ? g_hh_col : (which == 1) ? g_ih_col : g_ho_col;
    float* oval = (which == 0) ? g_hh_val : (which == 1) ? g_ih_val : g_ho_val;
    int i = blockIdx.x * blockDim.x + threadIdx.x;
    if (i >= nnz) return;
    int r = rows[i];
    int pos = atomicAdd(&g_cnt[r], 1);
    int idx = ptr[r] + pos;
    ocol[idx] = cols[i];
    oval[idx] = vals[i];
}

// ---------------- x transpose: (B,T,I) -> (T,I,B) ----------------
__global__ void transpose_kernel(const float* __restrict__ x) {
    __shared__ float tile[32][33];
    int t  = blockIdx.y;
    int i0 = blockIdx.x * 32;
    int tx = threadIdx.x, ty = threadIdx.y;
    // read coalesced over i:  x[b=ty][t][i0+tx]
    tile[ty][tx] = x[(size_t)ty * T * IDIM + (size_t)t * IDIM + i0 + tx];
    __syncthreads();
    // write coalesced over b: g_xT[t][i0+ty][b=tx]
    g_xT[(size_t)t * IDIM * B + (size_t)(i0 + ty) * B + tx] = tile[tx][ty];
}

// ---------------- warp-per-row CSR gather helper ----------------
__device__ __forceinline__ float csr_row_gather(const int* __restrict__ col,
                                                const float* __restrict__ val,
                                                int s, int e,
                                                const float* __restrict__ src,
                                                int lane) {
    float acc = 0.0f;
    int k = s;
    for (; k + 4 <= e; k += 4) {
        int c0 = __ldg(col + k);
        int c1 = __ldg(col + k + 1);
        int c2 = __ldg(col + k + 2);
        int c3 = __ldg(col + k + 3);
        float v0 = __ldg(val + k);
        float v1 = __ldg(val + k + 1);
        float v2 = __ldg(val + k + 2);
        float v3 = __ldg(val + k + 3);
        float x0 = __ldg(src + c0 * B + lane);
        float x1 = __ldg(src + c1 * B + lane);
        float x2 = __ldg(src + c2 * B + lane);
        float x3 = __ldg(src + c3 * B + lane);
        acc += v0 * x0;
        acc += v1 * x1;
        acc += v2 * x2;
        acc += v3 * x3;
    }
    for (; k < e; k++)
        acc += __ldg(val + k) * __ldg(src + __ldg(col + k) * B + lane);
    return acc;
}

// ---------------- ih @ x_t for all t (fully parallel) ----------------
__global__ void ih_kernel() {
    int w = (blockIdx.x * blockDim.x + threadIdx.x) >> 5;
    int lane = threadIdx.x & 31;
    if (w >= T * H) return;
    int r = w & (H - 1);
    int t = w >> 13;   // H = 2^13
    int s = g_ih_ptr[r], e = g_ih_ptr[r + 1];
    const float* __restrict__ xt = g_xT + (size_t)t * IDIM * B;
    float acc = csr_row_gather(g_ih_col, g_ih_val, s, e, xt, lane);
    g_pre[(size_t)w * B + lane] = acc;
}

// ---------------- fused recurrent step ----------------
// call t: warps [0,H)     compute h_t   = sigmoid(pre[t] + hh@h_{t-1} + hh_bias)  (if t < T)
//         warps [H,H+O)   compute out_{t-1} = ho@h_{t-1} + ho_bias                (if t >= 1)
// h_{t-1} lives in g_h[t&1]; h_t written to g_h[(t+1)&1]. g_h[0] zeroed before t=0.
__global__ void step_kernel(int t,
                            const float* __restrict__ hhb,
                            const float* __restrict__ hob,
                            float* __restrict__ out) {
    int w = (blockIdx.x * blockDim.x + threadIdx.x) >> 5;
    int lane = threadIdx.x & 31;
    const float* __restrict__ hin = g_h[t & 1];
    if (w < H) {
        if (t >= T) return;
        int r = w;
        float acc = g_pre[((size_t)t * H + r) * B + lane] + __ldg(hhb + r);
        int s = g_hh_ptr[r], e = g_hh_ptr[r + 1];
        acc += csr_row_gather(g_hh_col, g_hh_val, s, e, hin, lane);
        g_h[(t + 1) & 1][r * B + lane] = 1.0f / (1.0f + expf(-acc));
    } else if (w < H + ODIM) {
        if (t < 1) return;
        int r = w - H;
        float acc = __ldg(hob + r);
        int s = g_ho_ptr[r], e = g_ho_ptr[r + 1];
        acc += csr_row_gather(g_ho_col, g_ho_val, s, e, hin, lane);
        out[(size_t)lane * (T * ODIM) + (size_t)(t - 1) * ODIM + r] = acc;
    }
}

// ---------------- launch ----------------
extern "C" void kernel_launch(void* const* d_in, const int* in_sizes, int n_in,
                              void* d_out, int out_size) {
    const float* x       = (const float*)d_in[0];
    const int*   hh_rows = (const int*)  d_in[1];
    const int*   hh_cols = (const int*)  d_in[2];
    const float* hh_vals = (const float*)d_in[3];
    const float* hh_bias = (const float*)d_in[4];
    const int*   ih_rows = (const int*)  d_in[5];
    const int*   ih_cols = (const int*)  d_in[6];
    const float* ih_vals = (const float*)d_in[7];
    const int*   ho_rows = (const int*)  d_in[8];
    const int*   ho_cols = (const int*)  d_in[9];
    const float* ho_vals = (const float*)d_in[10];
    const float* ho_bias = (const float*)d_in[11];
    float* out = (float*)d_out;

    // x -> (T, I, B)
    transpose_kernel<<<dim3(IDIM / 32, T), dim3(32, 32)>>>(x);

    // build CSR for all three matrices
    // hh
    zero_cnt_kernel<<<H / 256, 256>>>();
    hist_kernel<<<(NNZ_HH + 255) / 256, 256>>>(hh_rows, NNZ_HH);
    scan_kernel<<<1, 1024>>>(0, H);
    zero_cnt_kernel<<<H / 256, 256>>>();
    scatter_kernel<<<(NNZ_HH + 255) / 256, 256>>>(hh_rows, hh_cols, hh_vals, 0, NNZ_HH);
    // ih
    zero_cnt_kernel<<<H / 256, 256>>>();
    hist_kernel<<<(NNZ_IH + 255) / 256, 256>>>(ih_rows, NNZ_IH);
    scan_kernel<<<1, 1024>>>(1, H);
    zero_cnt_kernel<<<H / 256, 256>>>();
    scatter_kernel<<<(NNZ_IH + 255) / 256, 256>>>(ih_rows, ih_cols, ih_vals, 1, NNZ_IH);
    // ho
    zero_cnt_kernel<<<H / 256, 256>>>();
    hist_kernel<<<(NNZ_HO + 255) / 256, 256>>>(ho_rows, NNZ_HO);
    scan_kernel<<<1, 1024>>>(2, ODIM);
    zero_cnt_kernel<<<H / 256, 256>>>();
    scatter_kernel<<<(NNZ_HO + 255) / 256, 256>>>(ho_rows, ho_cols, ho_vals, 2, NNZ_HO);

    // h_{-1} = 0
    zero_h_kernel<<<(H * B) / 256, 256>>>();

    // pre[t] = ih @ x_t for all t (parallel over T*H warps)
    ih_kernel<<<(T * H * 32) / 256, 256>>>();

    // sequential recurrence, out_{t-1} fused into step t
    int step_blocks = ((H + ODIM) * 32) / 256;
    for (int t = 0; t <= T; t++) {
        step_kernel<<<step_blocks, 256>>>(t, hh_bias, ho_bias, out);
    }
}

// round 2
// speedup vs baseline: 1.0908x; 1.0908x over previous
#include <cuda_runtime.h>

#define B 32
#define T 32
#define IDIM 8192
#define H 8192
#define ODIM 2048
#define NNZ_HH 1048576
#define NNZ_IH 524288
#define NNZ_HO 262144

#define PBLOCKS 888        // 148 SMs x 6 blocks, guaranteed co-resident
#define PTHREADS 256
#define PNWARPS ((PBLOCKS * PTHREADS) / 32)

// ---------------- device scratch (static, no runtime alloc) ----------------
__device__ float g_xT[(size_t)T * IDIM * B];    // (t, i, b)   32 MB
__device__ float g_pre[(size_t)T * H * B];      // ih@x_t      32 MB
__device__ float g_h[2][H * B];                 // ping-pong hidden
__device__ float g_outT[(size_t)T * ODIM * B];  // (t, o, b)   8 MB
__device__ int   g_cnt[H];
__device__ unsigned g_arrive;

__device__ int  g_hh_ptr[H + 1];
__device__ int2 g_hh_pair[NNZ_HH];   // packed {col, val-as-int}
__device__ int  g_ih_ptr[H + 1];
__device__ int2 g_ih_pair[NNZ_IH];
__device__ int  g_ho_ptr[ODIM + 1];
__device__ int2 g_ho_pair[NNZ_HO];

// ---------------- CSR build ----------------
__global__ void zero_cnt_kernel() {
    int i = blockIdx.x * blockDim.x + threadIdx.x;
    if (i < H) g_cnt[i] = 0;
}

__global__ void init_kernel() {   // zero h0 + barrier counter
    int i = blockIdx.x * blockDim.x + threadIdx.x;
    if (i < H * B) g_h[0][i] = 0.0f;
    if (i == 0) g_arrive = 0u;
}

__global__ void hist_kernel(const int* __restrict__ rows, int nnz) {
    int i = blockIdx.x * blockDim.x + threadIdx.x;
    if (i < nnz) atomicAdd(&g_cnt[rows[i]], 1);
}

// single-block exclusive scan of g_cnt[0..n) into selected ptr array
__global__ void scan_kernel(int which, int n) {
    __shared__ int s[1024];
    int* ptr = (which == 0) ? g_hh_ptr : (which == 1) ? g_ih_ptr : g_ho_ptr;
    int tid = threadIdx.x;
    int per = (n + 1023) >> 10;
    int base = tid * per;
    int local[8];
    int sum = 0;
    for (int j = 0; j < per; j++) {
        int v = (base + j < n) ? g_cnt[base + j] : 0;
        local[j] = sum;
        sum += v;
    }
    s[tid] = sum;
    __syncthreads();
    for (int off = 1; off < 1024; off <<= 1) {
        int v = (tid >= off) ? s[tid - off] : 0;
        __syncthreads();
        s[tid] += v;
        __syncthreads();
    }
    int excl = tid ? s[tid - 1] : 0;
    for (int j = 0; j < per; j++)
        if (base + j < n) ptr[base + j] = excl + local[j];
    if (tid == 1023) ptr[n] = s[1023];
}

__global__ void scatter_kernel(const int* __restrict__ rows,
                               const int* __restrict__ cols,
                               const float* __restrict__ vals,
                               int which, int nnz) {
    const int* ptr = (which == 0) ? g_hh_ptr : (which == 1) ? g_ih_ptr : g_ho_ptr;
    int2* opair = (which == 0) ? g_hh_pair : (which == 1) ? g_ih_pair : g_ho_pair;
    int i = blockIdx.x * blockDim.x + threadIdx.x;
    if (i >= nnz) return;
    int r = rows[i];
    int pos = atomicAdd(&g_cnt[r], 1);
    opair[ptr[r] + pos] = make_int2(cols[i], __float_as_int(vals[i]));
}

// ---------------- x transpose: (B,T,I) -> (T,I,B) ----------------
__global__ void transpose_kernel(const float* __restrict__ x) {
    __shared__ float tile[32][33];
    int t  = blockIdx.y;
    int i0 = blockIdx.x * 32;
    int tx = threadIdx.x, ty = threadIdx.y;
    tile[ty][tx] = x[(size_t)ty * T * IDIM + (size_t)t * IDIM + i0 + tx];
    __syncthreads();
    g_xT[(size_t)t * IDIM * B + (size_t)(i0 + ty) * B + tx] = tile[tx][ty];
}

// ---------------- shuffle-broadcast CSR row gather: ~1 LDG per nnz ----------
// Each lane holds one packed (col,val); shfl broadcasts them; lane = batch b.
template <bool CG>
__device__ __forceinline__ float pair_gather(const int2* __restrict__ pair,
                                             int s, int e,
                                             const float* __restrict__ src,
                                             int lane) {
    float acc = 0.0f;
    int k0 = s;
    for (; k0 + 32 <= e; k0 += 32) {
        int2 p = __ldg(pair + k0 + lane);
#pragma unroll
        for (int j = 0; j < 32; j += 4) {
            int c0 = __shfl_sync(0xffffffffu, p.x, j);
            int c1 = __shfl_sync(0xffffffffu, p.x, j + 1);
            int c2 = __shfl_sync(0xffffffffu, p.x, j + 2);
            int c3 = __shfl_sync(0xffffffffu, p.x, j + 3);
            float v0 = __int_as_float(__shfl_sync(0xffffffffu, p.y, j));
            float v1 = __int_as_float(__shfl_sync(0xffffffffu, p.y, j + 1));
            float v2 = __int_as_float(__shfl_sync(0xffffffffu, p.y, j + 2));
            float v3 = __int_as_float(__shfl_sync(0xffffffffu, p.y, j + 3));
            float x0 = CG ? __ldcg(src + c0 * B + lane) : __ldg(src + c0 * B + lane);
            float x1 = CG ? __ldcg(src + c1 * B + lane) : __ldg(src + c1 * B + lane);
            float x2 = CG ? __ldcg(src + c2 * B + lane) : __ldg(src + c2 * B + lane);
            float x3 = CG ? __ldcg(src + c3 * B + lane) : __ldg(src + c3 * B + lane);
            acc += v0 * x0;
            acc += v1 * x1;
            acc += v2 * x2;
            acc += v3 * x3;
        }
    }
    int rem = e - k0;
    if (rem > 0) {
        int2 p = make_int2(0, 0);
        if (lane < rem) p = __ldg(pair + k0 + lane);
        for (int j = 0; j < rem; j++) {
            int c = __shfl_sync(0xffffffffu, p.x, j);
            float v = __int_as_float(__shfl_sync(0xffffffffu, p.y, j));
            float xv = CG ? __ldcg(src + c * B + lane) : __ldg(src + c * B + lane);
            acc += v * xv;
        }
    }
    return acc;
}

// ---------------- ih @ x_t for all t (fully parallel) ----------------
__global__ void ih_kernel() {
    int w = (blockIdx.x * blockDim.x + threadIdx.x) >> 5;
    int lane = threadIdx.x & 31;
    if (w >= T * H) return;
    int r = w & (H - 1);
    int t = w >> 13;
    const float* __restrict__ xt = g_xT + (size_t)t * IDIM * B;
    float acc = pair_gather<false>(g_ih_pair, g_ih_ptr[r], g_ih_ptr[r + 1], xt, lane);
    g_pre[(size_t)w * B + lane] = acc;
}

// ---------------- persistent fused recurrence -------------------------------
// Step t: vwarps [0,H)   -> h_t = sigmoid(pre[t] + hh@h_{t-1} + hhb)   (t < T)
//         vwarps [H,H+O) -> out_{t-1} = ho@h_{t-1} + hob               (t >= 1)
// Grid barrier between steps (monotonic arrival counter, all blocks resident).
// h gathers use ld.global.cg (L2) — L1 is not coherent across in-kernel barriers.
__global__ void __launch_bounds__(PTHREADS, 6)
recur_kernel(const float* __restrict__ hhb,
             const float* __restrict__ hob) {
    int gwarp = (blockIdx.x * PTHREADS + threadIdx.x) >> 5;
    int lane = threadIdx.x & 31;
    unsigned target = 0;

    for (int t = 0; t <= T; t++) {
        const float* __restrict__ hin = g_h[t & 1];
        float* __restrict__ hout = g_h[(t + 1) & 1];

        for (int w = gwarp; w < H + ODIM; w += PNWARPS) {
            if (w < H) {
                if (t >= T) continue;
                float acc = g_pre[((size_t)t * H + w) * B + lane] + __ldg(hhb + w);
                acc += pair_gather<true>(g_hh_pair, g_hh_ptr[w], g_hh_ptr[w + 1], hin, lane);
                hout[w * B + lane] = 1.0f / (1.0f + __expf(-acc));
            } else {
                if (t == 0) continue;
                int r = w - H;
                float acc = __ldg(hob + r);
                acc += pair_gather<true>(g_ho_pair, g_ho_ptr[r], g_ho_ptr[r + 1], hin, lane);
                g_outT[((size_t)(t - 1) * ODIM + r) * B + lane] = acc;
            }
        }

        if (t < T) {   // grid barrier
            __threadfence();
            __syncthreads();
            target += PBLOCKS;
            if (threadIdx.x == 0) {
                atomicAdd(&g_arrive, 1u);
                while (*(volatile unsigned*)&g_arrive < target) { }
                __threadfence();
            }
            __syncthreads();
        }
    }
}

// ---------------- output transpose: (T,O,B) -> (B,T,O) ----------------------
__global__ void out_transpose_kernel(float* __restrict__ out) {
    __shared__ float tile[32][33];
    int t  = blockIdx.y;
    int o0 = blockIdx.x * 32;
    int tx = threadIdx.x, ty = threadIdx.y;
    // read coalesced over b (tx = b)
    tile[ty][tx] = g_outT[((size_t)t * ODIM + o0 + ty) * B + tx];
    __syncthreads();
    // write coalesced over o (tx = o_local, ty = b)
    out[(size_t)ty * (T * ODIM) + (size_t)t * ODIM + o0 + tx] = tile[tx][ty];
}

// ---------------- launch ----------------
extern "C" void kernel_launch(void* const* d_in, const int* in_sizes, int n_in,
                              void* d_out, int out_size) {
    const float* x       = (const float*)d_in[0];
    const int*   hh_rows = (const int*)  d_in[1];
    const int*   hh_cols = (const int*)  d_in[2];
    const float* hh_vals = (const float*)d_in[3];
    const float* hh_bias = (const float*)d_in[4];
    const int*   ih_rows = (const int*)  d_in[5];
    const int*   ih_cols = (const int*)  d_in[6];
    const float* ih_vals = (const float*)d_in[7];
    const int*   ho_rows = (const int*)  d_in[8];
    const int*   ho_cols = (const int*)  d_in[9];
    const float* ho_vals = (const float*)d_in[10];
    const float* ho_bias = (const float*)d_in[11];
    float* out = (float*)d_out;

    transpose_kernel<<<dim3(IDIM / 32, T), dim3(32, 32)>>>(x);

    // CSR builds
    zero_cnt_kernel<<<H / 256, 256>>>();
    hist_kernel<<<(NNZ_HH + 255) / 256, 256>>>(hh_rows, NNZ_HH);
    scan_kernel<<<1, 1024>>>(0, H);
    zero_cnt_kernel<<<H / 256, 256>>>();
    scatter_kernel<<<(NNZ_HH + 255) / 256, 256>>>(hh_rows, hh_cols, hh_vals, 0, NNZ_HH);

    zero_cnt_kernel<<<H / 256, 256>>>();
    hist_kernel<<<(NNZ_IH + 255) / 256, 256>>>(ih_rows, NNZ_IH);
    scan_kernel<<<1, 1024>>>(1, H);
    zero_cnt_kernel<<<H / 256, 256>>>();
    scatter_kernel<<<(NNZ_IH + 255) / 256, 256>>>(ih_rows, ih_cols, ih_vals, 1, NNZ_IH);

    zero_cnt_kernel<<<H / 256, 256>>>();
    hist_kernel<<<(NNZ_HO + 255) / 256, 256>>>(ho_rows, NNZ_HO);
    scan_kernel<<<1, 1024>>>(2, ODIM);
    zero_cnt_kernel<<<H / 256, 256>>>();
    scatter_kernel<<<(NNZ_HO + 255) / 256, 256>>>(ho_rows, ho_cols, ho_vals, 2, NNZ_HO);

    // h0 = 0, barrier counter = 0
    init_kernel<<<(H * B) / 256, 256>>>();

    // pre[t] = ih @ x_t for all t
    ih_kernel<<<(T * H * 32) / 256, 256>>>();

    // persistent fused recurrence (all T steps in one launch)
    recur_kernel<<<PBLOCKS, PTHREADS>>>(hh_bias, ho_bias);

    out_transpose_kernel<<<dim3(ODIM / 32, T), dim3(32, 32)>>>(out);
}

// round 3
// speedup vs baseline: 1.1097x; 1.0173x over previous
#include <cuda_runtime.h>

#define B 32
#define T 32
#define IDIM 8192
#define H 8192
#define ODIM 2048
#define NNZ_HH 1048576
#define NNZ_IH 524288
#define NNZ_HO 262144

#define RBLOCKS 592          // 148 SMs x 4 blocks of 512 thr -> 9472 warps >= 8192 rows
#define RTHREADS 512

// ---------------- device scratch (static, no runtime alloc) ----------------
__device__ float g_xT[(size_t)T * IDIM * B];      // (t, i, b)   32 MB
__device__ float g_pre[(size_t)T * H * B];        // hh_bias + ih@x_t, 32 MB
__device__ float g_hs[T + 1][H * B];              // h_0..h_T, 33 x 1MB (no reuse -> L1-safe)
__device__ float g_outT[(size_t)T * ODIM * B];    // (t, o, b)   8 MB
__device__ int   g_cntHH[H];
__device__ int   g_cntIH[H];
__device__ int   g_cntHO[ODIM];
__device__ unsigned g_arrive;

__device__ int  g_hh_ptr[H + 1];
__device__ int2 g_hh_pair[NNZ_HH];   // packed {col, val-as-int}
__device__ int  g_ih_ptr[H + 1];
__device__ int2 g_ih_pair[NNZ_IH];
__device__ int  g_ho_ptr[ODIM + 1];
__device__ int2 g_ho_pair[NNZ_HO];

// ---------------- prep: x transpose (B,T,I)->(T,I,B) + zero counters --------
__global__ void prep_kernel(const float* __restrict__ x) {
    if (blockIdx.x == IDIM / 32) {   // aux blocks: zero counters + barrier
        int i = blockIdx.y * 1024 + threadIdx.y * 32 + threadIdx.x;
        if (i < H) g_cntHH[i] = 0;
        if (i < H) g_cntIH[i] = 0;
        if (i < ODIM) g_cntHO[i] = 0;
        if (i == 0) g_arrive = 0u;
        return;
    }
    __shared__ float tile[32][33];
    int t  = blockIdx.y;
    int i0 = blockIdx.x * 32;
    int tx = threadIdx.x, ty = threadIdx.y;
    // read coalesced over i (ty = b)
    tile[ty][tx] = x[(size_t)ty * T * IDIM + (size_t)t * IDIM + i0 + tx];
    __syncthreads();
    // write coalesced over b (tx = b)
    g_xT[(size_t)t * IDIM * B + (size_t)(i0 + ty) * B + tx] = tile[tx][ty];
}

// ---------------- CSR build: fused hist over all three matrices -------------
__global__ void hist_all_kernel(const int* __restrict__ hh_rows,
                                const int* __restrict__ ih_rows,
                                const int* __restrict__ ho_rows) {
    int i = blockIdx.x * blockDim.x + threadIdx.x;
    if (i < NNZ_HH) atomicAdd(&g_cntHH[hh_rows[i]], 1);
    if (i < NNZ_IH) atomicAdd(&g_cntIH[ih_rows[i]], 1);
    if (i < NNZ_HO) atomicAdd(&g_cntHO[ho_rows[i]], 1);
}

// one block per matrix: exclusive scan cnt -> ptr, then rezero cnt for scatter
__global__ void scan_all_kernel() {
    __shared__ int s[1024];
    int* cnt; int* ptr; int n;
    if (blockIdx.x == 0)      { cnt = g_cntHH; ptr = g_hh_ptr; n = H; }
    else if (blockIdx.x == 1) { cnt = g_cntIH; ptr = g_ih_ptr; n = H; }
    else                      { cnt = g_cntHO; ptr = g_ho_ptr; n = ODIM; }
    int tid = threadIdx.x;
    int per = (n + 1023) >> 10;
    int base = tid * per;
    int local[8];
    int sum = 0;
    for (int j = 0; j < per; j++) {
        int v = (base + j < n) ? cnt[base + j] : 0;
        local[j] = sum;
        sum += v;
    }
    s[tid] = sum;
    __syncthreads();
    for (int off = 1; off < 1024; off <<= 1) {
        int v = (tid >= off) ? s[tid - off] : 0;
        __syncthreads();
        s[tid] += v;
        __syncthreads();
    }
    int excl = tid ? s[tid - 1] : 0;
    for (int j = 0; j < per; j++)
        if (base + j < n) ptr[base + j] = excl + local[j];
    if (tid == 1023) ptr[n] = s[1023];
    __syncthreads();
    for (int j = 0; j < per; j++)
        if (base + j < n) cnt[base + j] = 0;
}

__global__ void scatter_all_kernel(const int* __restrict__ hh_rows,
                                   const int* __restrict__ hh_cols,
                                   const float* __restrict__ hh_vals,
                                   const int* __restrict__ ih_rows,
                                   const int* __restrict__ ih_cols,
                                   const float* __restrict__ ih_vals,
                                   const int* __restrict__ ho_rows,
                                   const int* __restrict__ ho_cols,
                                   const float* __restrict__ ho_vals) {
    int i = blockIdx.x * blockDim.x + threadIdx.x;
    if (i < NNZ_HH) {
        int r = hh_rows[i];
        int pos = atomicAdd(&g_cntHH[r], 1);
        g_hh_pair[g_hh_ptr[r] + pos] = make_int2(hh_cols[i], __float_as_int(hh_vals[i]));
    }
    if (i < NNZ_IH) {
        int r = ih_rows[i];
        int pos = atomicAdd(&g_cntIH[r], 1);
        g_ih_pair[g_ih_ptr[r] + pos] = make_int2(ih_cols[i], __float_as_int(ih_vals[i]));
    }
    if (i < NNZ_HO) {
        int r = ho_rows[i];
        int pos = atomicAdd(&g_cntHO[r], 1);
        g_ho_pair[g_ho_ptr[r] + pos] = make_int2(ho_cols[i], __float_as_int(ho_vals[i]));
    }
}

// ---------------- shuffle-broadcast CSR row gather (~1 LDG per nnz) ---------
__device__ __forceinline__ float pair_gather(const int2* __restrict__ pair,
                                             int s, int e,
                                             const float* __restrict__ src,
                                             int lane) {
    float a0 = 0.f, a1 = 0.f, a2 = 0.f, a3 = 0.f;
    int k0 = s;
    for (; k0 + 32 <= e; k0 += 32) {
        int2 p = __ldg(pair + k0 + lane);
#pragma unroll
        for (int j = 0; j < 32; j += 4) {
            int c0 = __shfl_sync(0xffffffffu, p.x, j);
            int c1 = __shfl_sync(0xffffffffu, p.x, j + 1);
            int c2 = __shfl_sync(0xffffffffu, p.x, j + 2);
            int c3 = __shfl_sync(0xffffffffu, p.x, j + 3);
            float v0 = __int_as_float(__shfl_sync(0xffffffffu, p.y, j));
            float v1 = __int_as_float(__shfl_sync(0xffffffffu, p.y, j + 1));
            float v2 = __int_as_float(__shfl_sync(0xffffffffu, p.y, j + 2));
            float v3 = __int_as_float(__shfl_sync(0xffffffffu, p.y, j + 3));
            float x0 = __ldg(src + c0 * B + lane);
            float x1 = __ldg(src + c1 * B + lane);
            float x2 = __ldg(src + c2 * B + lane);
            float x3 = __ldg(src + c3 * B + lane);
            a0 += v0 * x0;
            a1 += v1 * x1;
            a2 += v2 * x2;
            a3 += v3 * x3;
        }
    }
    int rem = e - k0;
    if (rem > 0) {
        int2 p = (lane < rem) ? __ldg(pair + k0 + lane) : make_int2(0, 0);
        for (int j = 0; j < rem; j++) {
            int c = __shfl_sync(0xffffffffu, p.x, j);
            float v = __int_as_float(__shfl_sync(0xffffffffu, p.y, j));
            a0 += v * __ldg(src + c * B + lane);
        }
    }
    return (a0 + a1) + (a2 + a3);
}

// ---------------- ih @ x_t for all t (parallel) + zero h_0 ------------------
#define IH_BLOCKS ((T * H) / 8)   // 8 warps per 256-thr block
__global__ void ih_kernel(const float* __restrict__ hhb) {
    if (blockIdx.x >= IH_BLOCKS) {   // 32 aux blocks zero h_0
        int i = (blockIdx.x - IH_BLOCKS) * 256 + threadIdx.x;   // 8192 threads
        for (int j = i; j < H * B; j += 32 * 256) g_hs[0][j] = 0.f;
        return;
    }
    int w = (blockIdx.x * 256 + threadIdx.x) >> 5;
    int lane = threadIdx.x & 31;
    int r = w & (H - 1);
    int t = w >> 13;
    const float* __restrict__ xt = g_xT + (size_t)t * IDIM * B;
    float acc = __ldg(hhb + r)
              + pair_gather(g_ih_pair, g_ih_ptr[r], g_ih_ptr[r + 1], xt, lane);
    g_pre[(size_t)w * B + lane] = acc;    // w = t*H + r -> (t, r, b), bias folded in
}

// ---------------- persistent recurrence: hh only, 1 warp per row ------------
__global__ void __launch_bounds__(RTHREADS, 4)
recur_kernel() {
    int w = (blockIdx.x * RTHREADS + threadIdx.x) >> 5;
    int lane = threadIdx.x & 31;
    int s = 0, e = 0;
    if (w < H) { s = g_hh_ptr[w]; e = g_hh_ptr[w + 1]; }
    unsigned target = 0;

    for (int t = 0; t < T; t++) {
        if (w < H) {
            float acc = __ldg(&g_pre[((size_t)t * H + w) * B + lane]);
            acc += pair_gather(g_hh_pair, s, e, g_hs[t], lane);
            g_hs[t + 1][w * B + lane] = 1.0f / (1.0f + __expf(-acc));
        }
        if (t < T - 1) {   // grid barrier
            __threadfence();
            __syncthreads();
            target += RBLOCKS;
            if (threadIdx.x == 0) {
                atomicAdd(&g_arrive, 1u);
                while (*(volatile unsigned*)&g_arrive < target) { }
            }
            __syncthreads();
            __threadfence();
        }
    }
}

// ---------------- out_t = ho @ h_{t+1} + bias, all t parallel ----------------
__global__ void ho_kernel(const float* __restrict__ hob) {
    int w = (blockIdx.x * blockDim.x + threadIdx.x) >> 5;
    int lane = threadIdx.x & 31;
    if (w >= T * ODIM) return;
    int r = w & (ODIM - 1);
    int t = w >> 11;
    float acc = __ldg(hob + r)
              + pair_gather(g_ho_pair, g_ho_ptr[r], g_ho_ptr[r + 1], g_hs[t + 1], lane);
    g_outT[(size_t)w * B + lane] = acc;   // w = t*ODIM + r -> (t, o, b)
}

// ---------------- output transpose: (T,O,B) -> (B,T,O) ----------------------
__global__ void out_transpose_kernel(float* __restrict__ out) {
    __shared__ float tile[32][33];
    int t  = blockIdx.y;
    int o0 = blockIdx.x * 32;
    int tx = threadIdx.x, ty = threadIdx.y;
    tile[ty][tx] = g_outT[((size_t)t * ODIM + o0 + ty) * B + tx];
    __syncthreads();
    out[(size_t)ty * (T * ODIM) + (size_t)t * ODIM + o0 + tx] = tile[tx][ty];
}

// ---------------- launch ----------------
extern "C" void kernel_launch(void* const* d_in, const int* in_sizes, int n_in,
                              void* d_out, int out_size) {
    const float* x       = (const float*)d_in[0];
    const int*   hh_rows = (const int*)  d_in[1];
    const int*   hh_cols = (const int*)  d_in[2];
    const float* hh_vals = (const float*)d_in[3];
    const float* hh_bias = (const float*)d_in[4];
    const int*   ih_rows = (const int*)  d_in[5];
    const int*   ih_cols = (const int*)  d_in[6];
    const float* ih_vals = (const float*)d_in[7];
    const int*   ho_rows = (const int*)  d_in[8];
    const int*   ho_cols = (const int*)  d_in[9];
    const float* ho_vals = (const float*)d_in[10];
    const float* ho_bias = (const float*)d_in[11];
    float* out = (float*)d_out;

    // 1: transpose x + zero counters
    prep_kernel<<<dim3(IDIM / 32 + 1, 32), dim3(32, 32)>>>(x);
    // 2: histograms (all three matrices)
    hist_all_kernel<<<NNZ_HH / 256, 256>>>(hh_rows, ih_rows, ho_rows);
    // 3: scans (+ counter rezero)
    scan_all_kernel<<<3, 1024>>>();
    // 4: scatter into CSR pair arrays
    scatter_all_kernel<<<NNZ_HH / 256, 256>>>(hh_rows, hh_cols, hh_vals,
                                              ih_rows, ih_cols, ih_vals,
                                              ho_rows, ho_cols, ho_vals);
    // 5: pre[t] = hh_bias + ih @ x_t (parallel over t) + zero h_0
    ih_kernel<<<IH_BLOCKS + 32, 256>>>(hh_bias);
    // 6: sequential recurrence, one warp per row, grid barriers between steps
    recur_kernel<<<RBLOCKS, RTHREADS>>>();
    // 7: all outputs in parallel
    ho_kernel<<<(T * ODIM) / 8, 256>>>(ho_bias);
    // 8: (T,O,B) -> (B,T,O)
    out_transpose_kernel<<<dim3(ODIM / 32, T), dim3(32, 32)>>>(out);
}

// round 4
// speedup vs baseline: 1.2041x; 1.0851x over previous
#include <cuda_runtime.h>

#define B 32
#define T 32
#define IDIM 8192
#define H 8192
#define ODIM 2048
#define NNZ_HH 1048576
#define NNZ_IH 524288
#define NNZ_HO 262144

#define RBLOCKS 148          // exactly one CTA per SM (mode-W: minimal spread)
#define RTHREADS 1024
#define RWARPS ((RBLOCKS * RTHREADS) / 32)   // 4736

// ---------------- device scratch (static, zero-init at load) ----------------
__device__ float g_xT[(size_t)T * IDIM * B];      // (t, i, b)   32 MB
__device__ float g_pre[(size_t)T * H * B];        // hh_bias + ih@x_t
__device__ float g_hs[T + 1][H * B];              // h_0..h_T (distinct buffers)
__device__ float g_outT[(size_t)T * ODIM * B];    // (t, o, b)
__device__ int   g_cntHH[H];                      // zero at load; ho re-zeroes
__device__ int   g_cntIH[H];
__device__ int   g_cntHO[ODIM];
__device__ unsigned g_arrive;                     // reset by ih each call

__device__ int  g_hh_ptr[H + 1];
__device__ int2 g_hh_pair[NNZ_HH];   // packed {col, val-as-int}
__device__ int  g_ih_ptr[H + 1];
__device__ int2 g_ih_pair[NNZ_IH];
__device__ int  g_ho_ptr[ODIM + 1];
__device__ int2 g_ho_pair[NNZ_HO];

// ---------------- launch 1: histograms + x transpose (fused) ---------------
#define HIST_BLOCKS (NNZ_HH / 256)
__global__ void hist_prep_kernel(const int* __restrict__ hh_rows,
                                 const int* __restrict__ ih_rows,
                                 const int* __restrict__ ho_rows,
                                 const float* __restrict__ x) {
    if (blockIdx.x < HIST_BLOCKS) {
        int i = blockIdx.x * 256 + threadIdx.x;
        atomicAdd(&g_cntHH[hh_rows[i]], 1);
        if (i < NNZ_IH) atomicAdd(&g_cntIH[ih_rows[i]], 1);
        if (i < NNZ_HO) atomicAdd(&g_cntHO[ho_rows[i]], 1);
        return;
    }
    // transpose blocks: one 32x32 tile of (B,T,I)->(T,I,B) each
    __shared__ float tile[32][33];
    int bi = blockIdx.x - HIST_BLOCKS;         // 0 .. T*(IDIM/32)-1
    int t  = bi >> 8;                          // IDIM/32 = 256
    int i0 = (bi & 255) << 5;
    int tx = threadIdx.x & 31;
    int ty = threadIdx.x >> 5;                 // 0..7
    for (int bb = ty; bb < 32; bb += 8)
        tile[bb][tx] = x[(size_t)bb * T * IDIM + (size_t)t * IDIM + i0 + tx];
    __syncthreads();
    for (int ii = ty; ii < 32; ii += 8)
        g_xT[(size_t)t * IDIM * B + (size_t)(i0 + ii) * B + tx] = tile[tx][ii];
}

// ---------------- launch 2: scan cnt -> ptr, re-zero cnt for scatter --------
__global__ void scan_all_kernel() {
    __shared__ int s[1024];
    int* cnt; int* ptr; int n;
    if (blockIdx.x == 0)      { cnt = g_cntHH; ptr = g_hh_ptr; n = H; }
    else if (blockIdx.x == 1) { cnt = g_cntIH; ptr = g_ih_ptr; n = H; }
    else                      { cnt = g_cntHO; ptr = g_ho_ptr; n = ODIM; }
    int tid = threadIdx.x;
    int per = (n + 1023) >> 10;
    int base = tid * per;
    int local[8];
    int sum = 0;
    for (int j = 0; j < per; j++) {
        int v = (base + j < n) ? cnt[base + j] : 0;
        local[j] = sum;
        sum += v;
    }
    s[tid] = sum;
    __syncthreads();
    for (int off = 1; off < 1024; off <<= 1) {
        int v = (tid >= off) ? s[tid - off] : 0;
        __syncthreads();
        s[tid] += v;
        __syncthreads();
    }
    int excl = tid ? s[tid - 1] : 0;
    for (int j = 0; j < per; j++)
        if (base + j < n) ptr[base + j] = excl + local[j];
    if (tid == 1023) ptr[n] = s[1023];
    __syncthreads();
    for (int j = 0; j < per; j++)
        if (base + j < n) cnt[base + j] = 0;   // scatter reuses cnt as fill cursor
}

// ---------------- launch 3: scatter COO -> CSR pair arrays ------------------
__global__ void scatter_all_kernel(const int* __restrict__ hh_rows,
                                   const int* __restrict__ hh_cols,
                                   const float* __restrict__ hh_vals,
                                   const int* __restrict__ ih_rows,
                                   const int* __restrict__ ih_cols,
                                   const float* __restrict__ ih_vals,
                                   const int* __restrict__ ho_rows,
                                   const int* __restrict__ ho_cols,
                                   const float* __restrict__ ho_vals) {
    int i = blockIdx.x * blockDim.x + threadIdx.x;
    {
        int r = hh_rows[i];
        int pos = atomicAdd(&g_cntHH[r], 1);
        g_hh_pair[g_hh_ptr[r] + pos] = make_int2(hh_cols[i], __float_as_int(hh_vals[i]));
    }
    if (i < NNZ_IH) {
        int r = ih_rows[i];
        int pos = atomicAdd(&g_cntIH[r], 1);
        g_ih_pair[g_ih_ptr[r] + pos] = make_int2(ih_cols[i], __float_as_int(ih_vals[i]));
    }
    if (i < NNZ_HO) {
        int r = ho_rows[i];
        int pos = atomicAdd(&g_cntHO[r], 1);
        g_ho_pair[g_ho_ptr[r] + pos] = make_int2(ho_cols[i], __float_as_int(ho_vals[i]));
    }
}

// ---------------- shuffle-broadcast CSR row gather (~1 LDG/nnz, prefetch) ---
__device__ __forceinline__ float pair_gather(const int2* __restrict__ pair,
                                             int s, int e,
                                             const float* __restrict__ src,
                                             int lane) {
    float a0 = 0.f, a1 = 0.f, a2 = 0.f, a3 = 0.f;
    int nfull = (e - s) >> 5;
    int k0 = s;
    if (nfull > 0) {
        int2 p = __ldg(pair + k0 + lane);
        for (int blk = 0; blk < nfull; blk++) {
            int2 pn = p;
            if (blk + 1 < nfull) pn = __ldg(pair + k0 + 32 + lane);  // prefetch
#pragma unroll
            for (int j = 0; j < 32; j += 4) {
                int c0 = __shfl_sync(0xffffffffu, p.x, j);
                int c1 = __shfl_sync(0xffffffffu, p.x, j + 1);
                int c2 = __shfl_sync(0xffffffffu, p.x, j + 2);
                int c3 = __shfl_sync(0xffffffffu, p.x, j + 3);
                float v0 = __int_as_float(__shfl_sync(0xffffffffu, p.y, j));
                float v1 = __int_as_float(__shfl_sync(0xffffffffu, p.y, j + 1));
                float v2 = __int_as_float(__shfl_sync(0xffffffffu, p.y, j + 2));
                float v3 = __int_as_float(__shfl_sync(0xffffffffu, p.y, j + 3));
                a0 += v0 * __ldg(src + c0 * B + lane);
                a1 += v1 * __ldg(src + c1 * B + lane);
                a2 += v2 * __ldg(src + c2 * B + lane);
                a3 += v3 * __ldg(src + c3 * B + lane);
            }
            p = pn;
            k0 += 32;
        }
    }
    int rem = e - k0;
    if (rem > 0) {
        int2 p = (lane < rem) ? __ldg(pair + k0 + lane) : make_int2(0, 0);
        for (int j = 0; j < rem; j++) {
            int c = __shfl_sync(0xffffffffu, p.x, j);
            float v = __int_as_float(__shfl_sync(0xffffffffu, p.y, j));
            a0 += v * __ldg(src + c * B + lane);
        }
    }
    return (a0 + a1) + (a2 + a3);
}

// ---------------- launch 4: pre[t] = hh_bias + ih @ x_t (all t parallel) ----
#define IH_BLOCKS ((T * H) / 8)   // 8 warps/block, 1 row each
__global__ void ih_kernel(const float* __restrict__ hhb) {
    if (blockIdx.x >= IH_BLOCKS) {   // 32 aux blocks: zero h_0 + reset barrier
        int i = (blockIdx.x - IH_BLOCKS) * 256 + threadIdx.x;
        for (int j = i; j < H * B; j += 32 * 256) g_hs[0][j] = 0.f;
        if (i == 0) g_arrive = 0u;
        return;
    }
    int w = (blockIdx.x * 256 + threadIdx.x) >> 5;
    int lane = threadIdx.x & 31;
    int r = w & (H - 1);
    int t = w >> 13;
    const float* __restrict__ xt = g_xT + (size_t)t * IDIM * B;
    float acc = __ldg(hhb + r)
              + pair_gather(g_ih_pair, g_ih_ptr[r], g_ih_ptr[r + 1], xt, lane);
    g_pre[(size_t)w * B + lane] = acc;
}

// ---------------- launch 5: persistent recurrence, one CTA per SM -----------
__global__ void __launch_bounds__(RTHREADS, 1)
recur_kernel() {
    int gw = blockIdx.x * (RTHREADS / 32) + (threadIdx.x >> 5);
    int lane = threadIdx.x & 31;
    int r0 = gw;                 // always < 4736 < H
    int r1 = gw + RWARPS;        // second row, if < H
    int s0 = g_hh_ptr[r0], e0 = g_hh_ptr[r0 + 1];
    int s1 = 0, e1 = 0;
    if (r1 < H) { s1 = g_hh_ptr[r1]; e1 = g_hh_ptr[r1 + 1]; }
    unsigned target = 0;

    for (int t = 0; t < T; t++) {
        const float* __restrict__ hin = g_hs[t];
        float* __restrict__ hout = g_hs[t + 1];
        {
            float acc = __ldg(&g_pre[((size_t)t * H + r0) * B + lane]);
            acc += pair_gather(g_hh_pair, s0, e0, hin, lane);
            hout[r0 * B + lane] = 1.0f / (1.0f + __expf(-acc));
        }
        if (r1 < H) {
            float acc = __ldg(&g_pre[((size_t)t * H + r1) * B + lane]);
            acc += pair_gather(g_hh_pair, s1, e1, hin, lane);
            hout[r1 * B + lane] = 1.0f / (1.0f + __expf(-acc));
        }
        if (t < T - 1) {   // grid barrier (148 arrivals, nanosleep backoff)
            __threadfence();
            __syncthreads();
            target += RBLOCKS;
            if (threadIdx.x == 0) {
                atomicAdd(&g_arrive, 1u);
                while (*(volatile unsigned*)&g_arrive < target) __nanosleep(64);
            }
            __syncthreads();
            __threadfence();
        }
    }
}

// ---------------- launch 6: out = ho @ h_{t+1} (+ counter re-zero aux) ------
#define HO_BLOCKS ((T * ODIM) / 8)
__global__ void ho_kernel(const float* __restrict__ hob) {
    if (blockIdx.x >= HO_BLOCKS) {   // 32 aux blocks: re-zero counters for next call
        int i = (blockIdx.x - HO_BLOCKS) * 256 + threadIdx.x;
        if (i < H) g_cntHH[i] = 0;
        if (i < H) g_cntIH[i] = 0;
        if (i < ODIM) g_cntHO[i] = 0;
        return;
    }
    int w = (blockIdx.x * 256 + threadIdx.x) >> 5;
    int lane = threadIdx.x & 31;
    int r = w & (ODIM - 1);
    int t = w >> 11;
    float acc = __ldg(hob + r)
              + pair_gather(g_ho_pair, g_ho_ptr[r], g_ho_ptr[r + 1], g_hs[t + 1], lane);
    g_outT[(size_t)w * B + lane] = acc;
}

// ---------------- launch 7: (T,O,B) -> (B,T,O) ------------------------------
__global__ void out_transpose_kernel(float* __restrict__ out) {
    __shared__ float tile[32][33];
    int t  = blockIdx.y;
    int o0 = blockIdx.x * 32;
    int tx = threadIdx.x, ty = threadIdx.y;
    tile[ty][tx] = g_outT[((size_t)t * ODIM + o0 + ty) * B + tx];
    __syncthreads();
    out[(size_t)ty * (T * ODIM) + (size_t)t * ODIM + o0 + tx] = tile[tx][ty];
}

// ---------------- launch ----------------
extern "C" void kernel_launch(void* const* d_in, const int* in_sizes, int n_in,
                              void* d_out, int out_size) {
    const float* x       = (const float*)d_in[0];
    const int*   hh_rows = (const int*)  d_in[1];
    const int*   hh_cols = (const int*)  d_in[2];
    const float* hh_vals = (const float*)d_in[3];
    const float* hh_bias = (const float*)d_in[4];
    const int*   ih_rows = (const int*)  d_in[5];
    const int*   ih_cols = (const int*)  d_in[6];
    const float* ih_vals = (const float*)d_in[7];
    const int*   ho_rows = (const int*)  d_in[8];
    const int*   ho_cols = (const int*)  d_in[9];
    const float* ho_vals = (const float*)d_in[10];
    const float* ho_bias = (const float*)d_in[11];
    float* out = (float*)d_out;

    hist_prep_kernel<<<HIST_BLOCKS + T * (IDIM / 32), 256>>>(hh_rows, ih_rows, ho_rows, x);
    scan_all_kernel<<<3, 1024>>>();
    scatter_all_kernel<<<NNZ_HH / 256, 256>>>(hh_rows, hh_cols, hh_vals,
                                              ih_rows, ih_cols, ih_vals,
                                              ho_rows, ho_cols, ho_vals);
    ih_kernel<<<IH_BLOCKS + 32, 256>>>(hh_bias);
    recur_kernel<<<RBLOCKS, RTHREADS>>>();
    ho_kernel<<<HO_BLOCKS + 32, 256>>>(ho_bias);
    out_transpose_kernel<<<dim3(ODIM / 32, T), dim3(32, 32)>>>(out);
}

// round 5
// speedup vs baseline: 1.6145x; 1.3408x over previous
#include <cuda_runtime.h>

#define B 32
#define T 32
#define IDIM 8192
#define H 8192
#define ODIM 2048
#define NNZ_HH 1048576
#define NNZ_IH 524288
#define NNZ_HO 262144

#define RBLOCKS 148          // one CTA per SM
#define RTHREADS 1024
#define RWARPS ((RBLOCKS * RTHREADS) / 32)   // 4736

// ---------------- device scratch (static, zero-init at load) ----------------
__device__ float g_xT[(size_t)T * IDIM * B];      // (t, i, b)
__device__ float g_pre[(size_t)T * H * B];        // hh_bias + ih@x_t
__device__ float g_hs[T + 1][H * B];              // h_0..h_T (distinct buffers)
__device__ float g_outT[(size_t)T * ODIM * B];    // (t, o, b)
__device__ int   g_cntHH[H];
__device__ int   g_cntIH[H];
__device__ int   g_cntHO[ODIM];
__device__ unsigned g_arrive;

__device__ int  g_hh_ptr[H + 1];
__device__ int2 g_hh_pair[NNZ_HH];
__device__ int  g_ih_ptr[H + 1];
__device__ int2 g_ih_pair[NNZ_IH];
__device__ int  g_ho_ptr[ODIM + 1];
__device__ int2 g_ho_pair[NNZ_HO];

// ---------------- launch 1: histograms + x transpose (fused) ---------------
#define HIST_BLOCKS (NNZ_HH / 256)
__global__ void hist_prep_kernel(const int* __restrict__ hh_rows,
                                 const int* __restrict__ ih_rows,
                                 const int* __restrict__ ho_rows,
                                 const float* __restrict__ x) {
    if (blockIdx.x < HIST_BLOCKS) {
        int i = blockIdx.x * 256 + threadIdx.x;
        atomicAdd(&g_cntHH[hh_rows[i]], 1);
        if (i < NNZ_IH) atomicAdd(&g_cntIH[ih_rows[i]], 1);
        if (i < NNZ_HO) atomicAdd(&g_cntHO[ho_rows[i]], 1);
        return;
    }
    __shared__ float tile[32][33];
    int bi = blockIdx.x - HIST_BLOCKS;
    int t  = bi >> 8;
    int i0 = (bi & 255) << 5;
    int tx = threadIdx.x & 31;
    int ty = threadIdx.x >> 5;
    for (int bb = ty; bb < 32; bb += 8)
        tile[bb][tx] = x[(size_t)bb * T * IDIM + (size_t)t * IDIM + i0 + tx];
    __syncthreads();
    for (int ii = ty; ii < 32; ii += 8)
        g_xT[(size_t)t * IDIM * B + (size_t)(i0 + ii) * B + tx] = tile[tx][ii];
}

// ---------------- launch 2: scan cnt -> ptr, re-zero cnt --------------------
__global__ void scan_all_kernel() {
    __shared__ int s[1024];
    int* cnt; int* ptr; int n;
    if (blockIdx.x == 0)      { cnt = g_cntHH; ptr = g_hh_ptr; n = H; }
    else if (blockIdx.x == 1) { cnt = g_cntIH; ptr = g_ih_ptr; n = H; }
    else                      { cnt = g_cntHO; ptr = g_ho_ptr; n = ODIM; }
    int tid = threadIdx.x;
    int per = (n + 1023) >> 10;
    int base = tid * per;
    int local[8];
    int sum = 0;
    for (int j = 0; j < per; j++) {
        int v = (base + j < n) ? cnt[base + j] : 0;
        local[j] = sum;
        sum += v;
    }
    s[tid] = sum;
    __syncthreads();
    for (int off = 1; off < 1024; off <<= 1) {
        int v = (tid >= off) ? s[tid - off] : 0;
        __syncthreads();
        s[tid] += v;
        __syncthreads();
    }
    int excl = tid ? s[tid - 1] : 0;
    for (int j = 0; j < per; j++)
        if (base + j < n) ptr[base + j] = excl + local[j];
    if (tid == 1023) ptr[n] = s[1023];
    __syncthreads();
    for (int j = 0; j < per; j++)
        if (base + j < n) cnt[base + j] = 0;
}

// ---------------- launch 3: scatter COO -> CSR pair arrays ------------------
__global__ void scatter_all_kernel(const int* __restrict__ hh_rows,
                                   const int* __restrict__ hh_cols,
                                   const float* __restrict__ hh_vals,
                                   const int* __restrict__ ih_rows,
                                   const int* __restrict__ ih_cols,
                                   const float* __restrict__ ih_vals,
                                   const int* __restrict__ ho_rows,
                                   const int* __restrict__ ho_cols,
                                   const float* __restrict__ ho_vals) {
    int i = blockIdx.x * blockDim.x + threadIdx.x;
    {
        int r = hh_rows[i];
        int pos = atomicAdd(&g_cntHH[r], 1);
        g_hh_pair[g_hh_ptr[r] + pos] = make_int2(hh_cols[i], __float_as_int(hh_vals[i]));
    }
    if (i < NNZ_IH) {
        int r = ih_rows[i];
        int pos = atomicAdd(&g_cntIH[r], 1);
        g_ih_pair[g_ih_ptr[r] + pos] = make_int2(ih_cols[i], __float_as_int(ih_vals[i]));
    }
    if (i < NNZ_HO) {
        int r = ho_rows[i];
        int pos = atomicAdd(&g_cntHO[r], 1);
        g_ho_pair[g_ho_ptr[r] + pos] = make_int2(ho_cols[i], __float_as_int(ho_vals[i]));
    }
}

// ---------------- float4-quad gather ----------------------------------------
// Warp layout: lane = (sub, bq); sub = lane>>3 picks 1 of 4 concurrent nnz,
// bq = lane&7 picks a float4 of batch. One LDG.128 serves 4 nnz.
// acc in each lane covers b = bq*4..bq*4+3 for its sub's nnz subset.
__device__ __forceinline__ void f4fma(float v, float4 g, float4& a) {
    a.x += v * g.x; a.y += v * g.y; a.z += v * g.z; a.w += v * g.w;
}

// accumulate pairs [k0, e) into acc (no cross-sub reduce)
__device__ __forceinline__ void gather4_tail(const int2* __restrict__ pair,
                                             int k0, int e,
                                             const float4* __restrict__ src4,
                                             int lane, int sub, int bq,
                                             float4& acc) {
    for (; k0 + 32 <= e; k0 += 32) {
        int2 p = __ldg(pair + k0 + lane);
#pragma unroll
        for (int j = 0; j < 8; j++) {
            int idx = (j << 2) + sub;
            int c = __shfl_sync(0xffffffffu, p.x, idx);
            float v = __int_as_float(__shfl_sync(0xffffffffu, p.y, idx));
            float4 g = __ldg(src4 + c * 8 + bq);
            f4fma(v, g, acc);
        }
    }
    int rem = e - k0;
    if (rem > 0) {
        int2 p = make_int2(0, 0);
        if (lane < rem) p = __ldg(pair + k0 + lane);
        int nsub = (rem + 3) >> 2;
        for (int j = 0; j < nsub; j++) {
            int idx = (j << 2) + sub;
            int c = __shfl_sync(0xffffffffu, p.x, idx);
            float v = __int_as_float(__shfl_sync(0xffffffffu, p.y, idx));
            if (idx >= rem) v = 0.f;
            float4 g = __ldg(src4 + c * 8 + bq);
            f4fma(v, g, acc);
        }
    }
}

// reduce across the 4 sub groups (lanes xor 8, 16); result replicated per bq
__device__ __forceinline__ float4 xreduce(float4 a) {
#pragma unroll
    for (int m = 8; m <= 16; m <<= 1) {
        a.x += __shfl_xor_sync(0xffffffffu, a.x, m);
        a.y += __shfl_xor_sync(0xffffffffu, a.y, m);
        a.z += __shfl_xor_sync(0xffffffffu, a.z, m);
        a.w += __shfl_xor_sync(0xffffffffu, a.w, m);
    }
    return a;
}

// ---------------- launch 4: pre[t] = hh_bias + ih @ x_t ---------------------
#define IH_BLOCKS ((T * H) / 8)
__global__ void ih_kernel(const float* __restrict__ hhb) {
    if (blockIdx.x >= IH_BLOCKS) {
        int i = (blockIdx.x - IH_BLOCKS) * 256 + threadIdx.x;
        for (int j = i; j < H * B; j += 32 * 256) g_hs[0][j] = 0.f;
        if (i == 0) g_arrive = 0u;
        return;
    }
    int w = (blockIdx.x * 256 + threadIdx.x) >> 5;
    int lane = threadIdx.x & 31;
    int sub = lane >> 3, bq = lane & 7;
    int r = w & (H - 1);
    int t = w >> 13;
    const float4* __restrict__ xt4 = (const float4*)(g_xT + (size_t)t * IDIM * B);
    float4 acc = make_float4(0.f, 0.f, 0.f, 0.f);
    gather4_tail(g_ih_pair, g_ih_ptr[r], g_ih_ptr[r + 1], xt4, lane, sub, bq, acc);
    acc = xreduce(acc);
    float bias = __ldg(hhb + r);
    acc.x += bias; acc.y += bias; acc.z += bias; acc.w += bias;
    if (lane < 8) ((float4*)g_pre)[(size_t)w * 8 + lane] = acc;
}

// ---------------- launch 5: persistent recurrence ---------------------------
__global__ void __launch_bounds__(RTHREADS, 1)
recur_kernel() {
    int gw = blockIdx.x * (RTHREADS / 32) + (threadIdx.x >> 5);
    int lane = threadIdx.x & 31;
    int sub = lane >> 3, bq = lane & 7;
    int r0 = gw;
    int r1 = gw + RWARPS;
    bool two = (r1 < H);
    int s0 = g_hh_ptr[r0], e0 = g_hh_ptr[r0 + 1];
    int s1 = 0, e1 = 0;
    if (two) { s1 = g_hh_ptr[r1]; e1 = g_hh_ptr[r1 + 1]; }
    unsigned target = 0;

    for (int t = 0; t < T; t++) {
        const float4* __restrict__ hin4 = (const float4*)g_hs[t];
        float* __restrict__ hout = g_hs[t + 1];
        float4 A0 = make_float4(0.f, 0.f, 0.f, 0.f);
        float4 A1 = make_float4(0.f, 0.f, 0.f, 0.f);
        int k0 = s0, k1 = s1;

        if (two) {
            // joint full blocks: both rows' loads in flight together
            int nj = min(e0 - k0, e1 - k1) >> 5;
            for (int i = 0; i < nj; i++) {
                int2 p0 = __ldg(g_hh_pair + k0 + lane);
                int2 p1 = __ldg(g_hh_pair + k1 + lane);
#pragma unroll
                for (int j = 0; j < 8; j++) {
                    int idx = (j << 2) + sub;
                    int c0 = __shfl_sync(0xffffffffu, p0.x, idx);
                    float v0 = __int_as_float(__shfl_sync(0xffffffffu, p0.y, idx));
                    int c1 = __shfl_sync(0xffffffffu, p1.x, idx);
                    float v1 = __int_as_float(__shfl_sync(0xffffffffu, p1.y, idx));
                    float4 g0 = __ldg(hin4 + c0 * 8 + bq);
                    float4 g1 = __ldg(hin4 + c1 * 8 + bq);
                    f4fma(v0, g0, A0);
                    f4fma(v1, g1, A1);
                }
                k0 += 32; k1 += 32;
            }
        }
        gather4_tail(g_hh_pair, k0, e0, hin4, lane, sub, bq, A0);
        if (two) gather4_tail(g_hh_pair, k1, e1, hin4, lane, sub, bq, A1);

        A0 = xreduce(A0);
        if (two) A1 = xreduce(A1);

        {
            float4 pg = __ldcg((const float4*)(g_pre) + ((size_t)t * H + r0) * 8 + bq);
            float4 hv;
            hv.x = 1.0f / (1.0f + __expf(-(pg.x + A0.x)));
            hv.y = 1.0f / (1.0f + __expf(-(pg.y + A0.y)));
            hv.z = 1.0f / (1.0f + __expf(-(pg.z + A0.z)));
            hv.w = 1.0f / (1.0f + __expf(-(pg.w + A0.w)));
            if (lane < 8) ((float4*)hout)[r0 * 8 + lane] = hv;
        }
        if (two) {
            float4 pg = __ldcg((const float4*)(g_pre) + ((size_t)t * H + r1) * 8 + bq);
            float4 hv;
            hv.x = 1.0f / (1.0f + __expf(-(pg.x + A1.x)));
            hv.y = 1.0f / (1.0f + __expf(-(pg.y + A1.y)));
            hv.z = 1.0f / (1.0f + __expf(-(pg.z + A1.z)));
            hv.w = 1.0f / (1.0f + __expf(-(pg.w + A1.w)));
            if (lane < 8) ((float4*)hout)[r1 * 8 + lane] = hv;
        }

        if (t < T - 1) {   // grid barrier
            __threadfence();
            __syncthreads();
            target += RBLOCKS;
            if (threadIdx.x == 0) {
                atomicAdd(&g_arrive, 1u);
                while (*(volatile unsigned*)&g_arrive < target) __nanosleep(64);
            }
            __syncthreads();
            __threadfence();
        }
    }
}

// ---------------- launch 6: out = ho @ h_{t+1} (+ counter re-zero) ----------
#define HO_BLOCKS ((T * ODIM) / 8)
__global__ void ho_kernel(const float* __restrict__ hob) {
    if (blockIdx.x >= HO_BLOCKS) {
        int i = (blockIdx.x - HO_BLOCKS) * 256 + threadIdx.x;
        if (i < H) g_cntHH[i] = 0;
        if (i < H) g_cntIH[i] = 0;
        if (i < ODIM) g_cntHO[i] = 0;
        return;
    }
    int w = (blockIdx.x * 256 + threadIdx.x) >> 5;
    int lane = threadIdx.x & 31;
    int sub = lane >> 3, bq = lane & 7;
    int r = w & (ODIM - 1);
    int t = w >> 11;
    const float4* __restrict__ h4 = (const float4*)g_hs[t + 1];
    float4 acc = make_float4(0.f, 0.f, 0.f, 0.f);
    gather4_tail(g_ho_pair, g_ho_ptr[r], g_ho_ptr[r + 1], h4, lane, sub, bq, acc);
    acc = xreduce(acc);
    float bias = __ldg(hob + r);
    acc.x += bias; acc.y += bias; acc.z += bias; acc.w += bias;
    if (lane < 8) ((float4*)g_outT)[(size_t)w * 8 + lane] = acc;
}

// ---------------- launch 7: (T,O,B) -> (B,T,O) ------------------------------
__global__ void out_transpose_kernel(float* __restrict__ out) {
    __shared__ float tile[32][33];
    int t  = blockIdx.y;
    int o0 = blockIdx.x * 32;
    int tx = threadIdx.x, ty = threadIdx.y;
    tile[ty][tx] = g_outT[((size_t)t * ODIM + o0 + ty) * B + tx];
    __syncthreads();
    out[(size_t)ty * (T * ODIM) + (size_t)t * ODIM + o0 + tx] = tile[tx][ty];
}

// ---------------- launch ----------------
extern "C" void kernel_launch(void* const* d_in, const int* in_sizes, int n_in,
                              void* d_out, int out_size) {
    const float* x       = (const float*)d_in[0];
    const int*   hh_rows = (const int*)  d_in[1];
    const int*   hh_cols = (const int*)  d_in[2];
    const float* hh_vals = (const float*)d_in[3];
    const float* hh_bias = (const float*)d_in[4];
    const int*   ih_rows = (const int*)  d_in[5];
    const int*   ih_cols = (const int*)  d_in[6];
    const float* ih_vals = (const float*)d_in[7];
    const int*   ho_rows = (const int*)  d_in[8];
    const int*   ho_cols = (const int*)  d_in[9];
    const float* ho_vals = (const float*)d_in[10];
    const float* ho_bias = (const float*)d_in[11];
    float* out = (float*)d_out;

    hist_prep_kernel<<<HIST_BLOCKS + T * (IDIM / 32), 256>>>(hh_rows, ih_rows, ho_rows, x);
    scan_all_kernel<<<3, 1024>>>();
    scatter_all_kernel<<<NNZ_HH / 256, 256>>>(hh_rows, hh_cols, hh_vals,
                                              ih_rows, ih_cols, ih_vals,
                                              ho_rows, ho_cols, ho_vals);
    ih_kernel<<<IH_BLOCKS + 32, 256>>>(hh_bias);
    recur_kernel<<<RBLOCKS, RTHREADS>>>();
    ho_kernel<<<HO_BLOCKS + 32, 256>>>(ho_bias);
    out_transpose_kernel<<<dim3(ODIM / 32, T), dim3(32, 32)>>>(out);
}

// round 6
// speedup vs baseline: 1.7514x; 1.0848x over previous
#include <cuda_runtime.h>
#include <cuda_fp16.h>

#define B 32
#define T 32
#define IDIM 8192
#define H 8192
#define ODIM 2048
#define NNZ_HH 1048576
#define NNZ_IH 524288
#define NNZ_HO 262144

#define RBLOCKS 148          // one CTA per SM
#define RTHREADS 1024
#define RWARPS ((RBLOCKS * RTHREADS) / 32)   // 4736

// ---------------- device scratch (static, zero-init at load) ----------------
__device__ __half g_xTh[(size_t)T * IDIM * B];    // (t, i, b) fp16, 16 MB
__device__ float  g_pre[(size_t)T * H * B];       // hh_bias + ih@x_t (fp32)
__device__ __half g_hsH[T + 1][H * B];            // h_0..h_T fp16 (gathered operand)
__device__ float  g_outT[(size_t)T * ODIM * B];   // (t, o, b)
__device__ int    g_cntHH[H];
__device__ int    g_cntIH[H];
__device__ int    g_cntHO[ODIM];
__device__ unsigned g_arrive;

__device__ int  g_hh_ptr[H + 1];
__device__ int2 g_hh_pair[NNZ_HH];
__device__ int  g_ih_ptr[H + 1];
__device__ int2 g_ih_pair[NNZ_IH];
__device__ int  g_ho_ptr[ODIM + 1];
__device__ int2 g_ho_pair[NNZ_HO];

// ---------------- launch 1: histograms + x transpose->fp16 (fused) ----------
#define HIST_BLOCKS (NNZ_HH / 256)
__global__ void hist_prep_kernel(const int* __restrict__ hh_rows,
                                 const int* __restrict__ ih_rows,
                                 const int* __restrict__ ho_rows,
                                 const float* __restrict__ x) {
    if (blockIdx.x < HIST_BLOCKS) {
        int i = blockIdx.x * 256 + threadIdx.x;
        atomicAdd(&g_cntHH[hh_rows[i]], 1);
        if (i < NNZ_IH) atomicAdd(&g_cntIH[ih_rows[i]], 1);
        if (i < NNZ_HO) atomicAdd(&g_cntHO[ho_rows[i]], 1);
        return;
    }
    __shared__ float tile[32][33];
    int bi = blockIdx.x - HIST_BLOCKS;
    int t  = bi >> 8;
    int i0 = (bi & 255) << 5;
    int tx = threadIdx.x & 31;
    int ty = threadIdx.x >> 5;
    for (int bb = ty; bb < 32; bb += 8)
        tile[bb][tx] = x[(size_t)bb * T * IDIM + (size_t)t * IDIM + i0 + tx];
    __syncthreads();
    for (int ii = ty; ii < 32; ii += 8)
        g_xTh[(size_t)t * IDIM * B + (size_t)(i0 + ii) * B + tx] = __float2half(tile[tx][ii]);
}

// ---------------- launch 2: scan cnt -> ptr, re-zero cnt --------------------
__global__ void scan_all_kernel() {
    __shared__ int s[1024];
    int* cnt; int* ptr; int n;
    if (blockIdx.x == 0)      { cnt = g_cntHH; ptr = g_hh_ptr; n = H; }
    else if (blockIdx.x == 1) { cnt = g_cntIH; ptr = g_ih_ptr; n = H; }
    else                      { cnt = g_cntHO; ptr = g_ho_ptr; n = ODIM; }
    int tid = threadIdx.x;
    int per = (n + 1023) >> 10;
    int base = tid * per;
    int local[8];
    int sum = 0;
    for (int j = 0; j < per; j++) {
        int v = (base + j < n) ? cnt[base + j] : 0;
        local[j] = sum;
        sum += v;
    }
    s[tid] = sum;
    __syncthreads();
    for (int off = 1; off < 1024; off <<= 1) {
        int v = (tid >= off) ? s[tid - off] : 0;
        __syncthreads();
        s[tid] += v;
        __syncthreads();
    }
    int excl = tid ? s[tid - 1] : 0;
    for (int j = 0; j < per; j++)
        if (base + j < n) ptr[base + j] = excl + local[j];
    if (tid == 1023) ptr[n] = s[1023];
    __syncthreads();
    for (int j = 0; j < per; j++)
        if (base + j < n) cnt[base + j] = 0;
}

// ---------------- launch 3: scatter COO -> CSR pair arrays ------------------
__global__ void scatter_all_kernel(const int* __restrict__ hh_rows,
                                   const int* __restrict__ hh_cols,
                                   const float* __restrict__ hh_vals,
                                   const int* __restrict__ ih_rows,
                                   const int* __restrict__ ih_cols,
                                   const float* __restrict__ ih_vals,
                                   const int* __restrict__ ho_rows,
                                   const int* __restrict__ ho_cols,
                                   const float* __restrict__ ho_vals) {
    int i = blockIdx.x * blockDim.x + threadIdx.x;
    {
        int r = hh_rows[i];
        int pos = atomicAdd(&g_cntHH[r], 1);
        g_hh_pair[g_hh_ptr[r] + pos] = make_int2(hh_cols[i], __float_as_int(hh_vals[i]));
    }
    if (i < NNZ_IH) {
        int r = ih_rows[i];
        int pos = atomicAdd(&g_cntIH[r], 1);
        g_ih_pair[g_ih_ptr[r] + pos] = make_int2(ih_cols[i], __float_as_int(ih_vals[i]));
    }
    if (i < NNZ_HO) {
        int r = ho_rows[i];
        int pos = atomicAdd(&g_cntHO[r], 1);
        g_ho_pair[g_ho_ptr[r] + pos] = make_int2(ho_cols[i], __float_as_int(ho_vals[i]));
    }
}

// ---------------- fp16-quad gather -------------------------------------------
// Warp layout: sub = lane>>3 (4 concurrent nnz), bq = lane&7 (4 batch vals each).
// One LDG.64 per lane serves 4 nnz (64B per nnz row of 32 halfs).
__device__ __forceinline__ void h4fma(float v, uint2 g, float4& a) {
    float2 f01 = __half22float2(*reinterpret_cast<__half2*>(&g.x));
    float2 f23 = __half22float2(*reinterpret_cast<__half2*>(&g.y));
    a.x += v * f01.x; a.y += v * f01.y; a.z += v * f23.x; a.w += v * f23.y;
}

__device__ __forceinline__ void gather4h(const int2* __restrict__ pair,
                                         int k0, int e,
                                         const uint2* __restrict__ src2,
                                         int lane, int sub, int bq,
                                         float4& acc) {
    for (; k0 + 32 <= e; k0 += 32) {
        int2 p = __ldg(pair + k0 + lane);
#pragma unroll
        for (int j = 0; j < 8; j++) {
            int idx = (j << 2) + sub;
            int c = __shfl_sync(0xffffffffu, p.x, idx);
            float v = __int_as_float(__shfl_sync(0xffffffffu, p.y, idx));
            uint2 g = __ldg(src2 + c * 8 + bq);
            h4fma(v, g, acc);
        }
    }
    int rem = e - k0;
    if (rem > 0) {
        int2 p = make_int2(0, 0);
        if (lane < rem) p = __ldg(pair + k0 + lane);
        int nsub = (rem + 3) >> 2;
        for (int j = 0; j < nsub; j++) {
            int idx = (j << 2) + sub;
            int c = __shfl_sync(0xffffffffu, p.x, idx);
            float v = __int_as_float(__shfl_sync(0xffffffffu, p.y, idx));
            if (idx >= rem) v = 0.f;
            uint2 g = __ldg(src2 + c * 8 + bq);
            h4fma(v, g, acc);
        }
    }
}

// reduce across the 4 sub groups (lanes xor 8, 16)
__device__ __forceinline__ float4 xreduce(float4 a) {
#pragma unroll
    for (int m = 8; m <= 16; m <<= 1) {
        a.x += __shfl_xor_sync(0xffffffffu, a.x, m);
        a.y += __shfl_xor_sync(0xffffffffu, a.y, m);
        a.z += __shfl_xor_sync(0xffffffffu, a.z, m);
        a.w += __shfl_xor_sync(0xffffffffu, a.w, m);
    }
    return a;
}

// pack 4 floats -> 4 halfs in uint2
__device__ __forceinline__ uint2 pack4h(float4 f) {
    __half2 lo = __floats2half2_rn(f.x, f.y);
    __half2 hi = __floats2half2_rn(f.z, f.w);
    uint2 u;
    u.x = *reinterpret_cast<unsigned*>(&lo);
    u.y = *reinterpret_cast<unsigned*>(&hi);
    return u;
}

// ---------------- launch 4: pre[t] = hh_bias + ih @ x_t ---------------------
#define IH_BLOCKS ((T * H) / 8)
__global__ void ih_kernel(const float* __restrict__ hhb) {
    if (blockIdx.x >= IH_BLOCKS) {   // aux: zero h_0 (half zeros) + reset barrier
        int i = (blockIdx.x - IH_BLOCKS) * 256 + threadIdx.x;
        unsigned* h0 = (unsigned*)g_hsH[0];
        for (int j = i; j < (H * B) / 2; j += 32 * 256) h0[j] = 0u;
        if (i == 0) g_arrive = 0u;
        return;
    }
    int w = (blockIdx.x * 256 + threadIdx.x) >> 5;
    int lane = threadIdx.x & 31;
    int sub = lane >> 3, bq = lane & 7;
    int r = w & (H - 1);
    int t = w >> 13;
    const uint2* __restrict__ xt2 = (const uint2*)(g_xTh + (size_t)t * IDIM * B);
    float4 acc = make_float4(0.f, 0.f, 0.f, 0.f);
    gather4h(g_ih_pair, g_ih_ptr[r], g_ih_ptr[r + 1], xt2, lane, sub, bq, acc);
    acc = xreduce(acc);
    float bias = __ldg(hhb + r);
    acc.x += bias; acc.y += bias; acc.z += bias; acc.w += bias;
    if (lane < 8) ((float4*)g_pre)[(size_t)w * 8 + lane] = acc;
}

// ---------------- launch 5: persistent recurrence ---------------------------
__global__ void __launch_bounds__(RTHREADS, 1)
recur_kernel() {
    int gw = blockIdx.x * (RTHREADS / 32) + (threadIdx.x >> 5);
    int lane = threadIdx.x & 31;
    int sub = lane >> 3, bq = lane & 7;
    int r0 = gw;
    int r1 = gw + RWARPS;
    bool two = (r1 < H);
    int s0 = g_hh_ptr[r0], e0 = g_hh_ptr[r0 + 1];
    int s1 = 0, e1 = 0;
    if (two) { s1 = g_hh_ptr[r1]; e1 = g_hh_ptr[r1 + 1]; }
    unsigned target = 0;

    for (int t = 0; t < T; t++) {
        const uint2* __restrict__ hin2 = (const uint2*)g_hsH[t];
        uint2* __restrict__ hout2 = (uint2*)g_hsH[t + 1];
        float4 A0 = make_float4(0.f, 0.f, 0.f, 0.f);
        float4 A1 = make_float4(0.f, 0.f, 0.f, 0.f);
        int k0 = s0, k1 = s1;

        if (two) {   // joint blocks: both rows' loads in flight together
            int nj = min(e0 - k0, e1 - k1) >> 5;
            for (int i = 0; i < nj; i++) {
                int2 p0 = __ldg(g_hh_pair + k0 + lane);
                int2 p1 = __ldg(g_hh_pair + k1 + lane);
#pragma unroll
                for (int j = 0; j < 8; j++) {
                    int idx = (j << 2) + sub;
                    int c0 = __shfl_sync(0xffffffffu, p0.x, idx);
                    float v0 = __int_as_float(__shfl_sync(0xffffffffu, p0.y, idx));
                    int c1 = __shfl_sync(0xffffffffu, p1.x, idx);
                    float v1 = __int_as_float(__shfl_sync(0xffffffffu, p1.y, idx));
                    uint2 g0 = __ldg(hin2 + c0 * 8 + bq);
                    uint2 g1 = __ldg(hin2 + c1 * 8 + bq);
                    h4fma(v0, g0, A0);
                    h4fma(v1, g1, A1);
                }
                k0 += 32; k1 += 32;
            }
        }
        gather4h(g_hh_pair, k0, e0, hin2, lane, sub, bq, A0);
        if (two) gather4h(g_hh_pair, k1, e1, hin2, lane, sub, bq, A1);

        A0 = xreduce(A0);
        if (two) A1 = xreduce(A1);

        {
            float4 pg = __ldcg((const float4*)(g_pre) + ((size_t)t * H + r0) * 8 + bq);
            float4 hv;
            hv.x = 1.0f / (1.0f + __expf(-(pg.x + A0.x)));
            hv.y = 1.0f / (1.0f + __expf(-(pg.y + A0.y)));
            hv.z = 1.0f / (1.0f + __expf(-(pg.z + A0.z)));
            hv.w = 1.0f / (1.0f + __expf(-(pg.w + A0.w)));
            if (lane < 8) hout2[r0 * 8 + lane] = pack4h(hv);
        }
        if (two) {
            float4 pg = __ldcg((const float4*)(g_pre) + ((size_t)t * H + r1) * 8 + bq);
            float4 hv;
            hv.x = 1.0f / (1.0f + __expf(-(pg.x + A1.x)));
            hv.y = 1.0f / (1.0f + __expf(-(pg.y + A1.y)));
            hv.z = 1.0f / (1.0f + __expf(-(pg.z + A1.z)));
            hv.w = 1.0f / (1.0f + __expf(-(pg.w + A1.w)));
            if (lane < 8) hout2[r1 * 8 + lane] = pack4h(hv);
        }

        if (t < T - 1) {   // grid barrier
            __threadfence();
            __syncthreads();
            target += RBLOCKS;
            if (threadIdx.x == 0) {
                atomicAdd(&g_arrive, 1u);
                while (*(volatile unsigned*)&g_arrive < target) __nanosleep(64);
            }
            __syncthreads();
            __threadfence();
        }
    }
}

// ---------------- launch 6: out = ho @ h_{t+1} (+ counter re-zero) ----------
#define HO_BLOCKS ((T * ODIM) / 8)
__global__ void ho_kernel(const float* __restrict__ hob) {
    if (blockIdx.x >= HO_BLOCKS) {
        int i = (blockIdx.x - HO_BLOCKS) * 256 + threadIdx.x;
        if (i < H) g_cntHH[i] = 0;
        if (i < H) g_cntIH[i] = 0;
        if (i < ODIM) g_cntHO[i] = 0;
        return;
    }
    int w = (blockIdx.x * 256 + threadIdx.x) >> 5;
    int lane = threadIdx.x & 31;
    int sub = lane >> 3, bq = lane & 7;
    int r = w & (ODIM - 1);
    int t = w >> 11;
    const uint2* __restrict__ h2 = (const uint2*)g_hsH[t + 1];
    float4 acc = make_float4(0.f, 0.f, 0.f, 0.f);
    gather4h(g_ho_pair, g_ho_ptr[r], g_ho_ptr[r + 1], h2, lane, sub, bq, acc);
    acc = xreduce(acc);
    float bias = __ldg(hob + r);
    acc.x += bias; acc.y += bias; acc.z += bias; acc.w += bias;
    if (lane < 8) ((float4*)g_outT)[(size_t)w * 8 + lane] = acc;
}

// ---------------- launch 7: (T,O,B) -> (B,T,O) ------------------------------
__global__ void out_transpose_kernel(float* __restrict__ out) {
    __shared__ float tile[32][33];
    int t  = blockIdx.y;
    int o0 = blockIdx.x * 32;
    int tx = threadIdx.x, ty = threadIdx.y;
    tile[ty][tx] = g_outT[((size_t)t * ODIM + o0 + ty) * B + tx];
    __syncthreads();
    out[(size_t)ty * (T * ODIM) + (size_t)t * ODIM + o0 + tx] = tile[tx][ty];
}

// ---------------- launch ----------------
extern "C" void kernel_launch(void* const* d_in, const int* in_sizes, int n_in,
                              void* d_out, int out_size) {
    const float* x       = (const float*)d_in[0];
    const int*   hh_rows = (const int*)  d_in[1];
    const int*   hh_cols = (const int*)  d_in[2];
    const float* hh_vals = (const float*)d_in[3];
    const float* hh_bias = (const float*)d_in[4];
    const int*   ih_rows = (const int*)  d_in[5];
    const int*   ih_cols = (const int*)  d_in[6];
    const float* ih_vals = (const float*)d_in[7];
    const int*   ho_rows = (const int*)  d_in[8];
    const int*   ho_cols = (const int*)  d_in[9];
    const float* ho_vals = (const float*)d_in[10];
    const float* ho_bias = (const float*)d_in[11];
    float* out = (float*)d_out;

    hist_prep_kernel<<<HIST_BLOCKS + T * (IDIM / 32), 256>>>(hh_rows, ih_rows, ho_rows, x);
    scan_all_kernel<<<3, 1024>>>();
    scatter_all_kernel<<<NNZ_HH / 256, 256>>>(hh_rows, hh_cols, hh_vals,
                                              ih_rows, ih_cols, ih_vals,
                                              ho_rows, ho_cols, ho_vals);
    ih_kernel<<<IH_BLOCKS + 32, 256>>>(hh_bias);
    recur_kernel<<<RBLOCKS, RTHREADS>>>();
    ho_kernel<<<HO_BLOCKS + 32, 256>>>(ho_bias);
    out_transpose_kernel<<<dim3(ODIM / 32, T), dim3(32, 32)>>>(out);
}

// round 7
// speedup vs baseline: 1.9567x; 1.1172x over previous
#include <cuda_runtime.h>
#include <cuda_fp16.h>

#define B 32
#define T 32
#define IDIM 8192
#define H 8192
#define ODIM 2048
#define NNZ_HH 1048576
#define NNZ_IH 524288
#define NNZ_HO 262144

#define RBLOCKS 148
#define RTHREADS 1024
#define RWARPS ((RBLOCKS * RTHREADS) / 32)   // 4736
#define NSINGLE (2 * RWARPS - H)             // 1280 warps carry one row

// ---------------- device scratch (static, zero-init at load) ----------------
__device__ __half g_xTh[(size_t)T * IDIM * B];    // (t, i, b) fp16
__device__ float  g_pre[(size_t)T * H * B];       // hh_bias + ih@x_t (fp32)
__device__ __half g_hsH[T + 1][H * B];            // h_0..h_T fp16
__device__ float  g_outT[(size_t)T * ODIM * B];   // (t, o, b)
__device__ int    g_cntHH[H];
__device__ int    g_cntIH[H];
__device__ int    g_cntHO[ODIM];
__device__ unsigned g_arrive;
__device__ unsigned g_cursor;
__device__ int    g_order[H];                     // hh rows sorted by nnz asc

__device__ int  g_hh_ptr[H + 1];
__device__ int2 g_hh_pair[NNZ_HH];
__device__ int  g_ih_ptr[H + 1];
__device__ int2 g_ih_pair[NNZ_IH];
__device__ int  g_ho_ptr[ODIM + 1];
__device__ int2 g_ho_pair[NNZ_HO];

// ---------------- launch 1: histograms + x transpose->fp16 ------------------
#define HIST_BLOCKS (NNZ_HH / 256)
__global__ void hist_prep_kernel(const int* __restrict__ hh_rows,
                                 const int* __restrict__ ih_rows,
                                 const int* __restrict__ ho_rows,
                                 const float* __restrict__ x) {
    if (blockIdx.x < HIST_BLOCKS) {
        int i = blockIdx.x * 256 + threadIdx.x;
        atomicAdd(&g_cntHH[hh_rows[i]], 1);
        if (i < NNZ_IH) atomicAdd(&g_cntIH[ih_rows[i]], 1);
        if (i < NNZ_HO) atomicAdd(&g_cntHO[ho_rows[i]], 1);
        return;
    }
    __shared__ float tile[32][33];
    int bi = blockIdx.x - HIST_BLOCKS;
    int t  = bi >> 8;
    int i0 = (bi & 255) << 5;
    int tx = threadIdx.x & 31;
    int ty = threadIdx.x >> 5;
    for (int bb = ty; bb < 32; bb += 8)
        tile[bb][tx] = x[(size_t)bb * T * IDIM + (size_t)t * IDIM + i0 + tx];
    __syncthreads();
    for (int ii = ty; ii < 32; ii += 8)
        g_xTh[(size_t)t * IDIM * B + (size_t)(i0 + ii) * B + tx] = __float2half(tile[tx][ii]);
}

// ---------------- launch 2: scan cnt -> ptr, re-zero cnt --------------------
__global__ void scan_all_kernel() {
    __shared__ int s[1024];
    int* cnt; int* ptr; int n;
    if (blockIdx.x == 0)      { cnt = g_cntHH; ptr = g_hh_ptr; n = H; }
    else if (blockIdx.x == 1) { cnt = g_cntIH; ptr = g_ih_ptr; n = H; }
    else                      { cnt = g_cntHO; ptr = g_ho_ptr; n = ODIM; }
    int tid = threadIdx.x;
    int per = (n + 1023) >> 10;
    int base = tid * per;
    int local[8];
    int sum = 0;
    for (int j = 0; j < per; j++) {
        int v = (base + j < n) ? cnt[base + j] : 0;
        local[j] = sum;
        sum += v;
    }
    s[tid] = sum;
    __syncthreads();
    for (int off = 1; off < 1024; off <<= 1) {
        int v = (tid >= off) ? s[tid - off] : 0;
        __syncthreads();
        s[tid] += v;
        __syncthreads();
    }
    int excl = tid ? s[tid - 1] : 0;
    for (int j = 0; j < per; j++)
        if (base + j < n) ptr[base + j] = excl + local[j];
    if (tid == 1023) ptr[n] = s[1023];
    __syncthreads();
    for (int j = 0; j < per; j++)
        if (base + j < n) cnt[base + j] = 0;
}

// ---------------- launch 3: scatter COO -> CSR + reset h0/cursor/arrive -----
__global__ void scatter_all_kernel(const int* __restrict__ hh_rows,
                                   const int* __restrict__ hh_cols,
                                   const float* __restrict__ hh_vals,
                                   const int* __restrict__ ih_rows,
                                   const int* __restrict__ ih_cols,
                                   const float* __restrict__ ih_vals,
                                   const int* __restrict__ ho_rows,
                                   const int* __restrict__ ho_cols,
                                   const float* __restrict__ ho_vals) {
    if (blockIdx.x >= HIST_BLOCKS) {   // 32 aux blocks: zero h0 (fp16) + counters
        int i = (blockIdx.x - HIST_BLOCKS) * 256 + threadIdx.x;   // 0..8191
        uint4* h0 = (uint4*)g_hsH[0];
        uint4 z = make_uint4(0u, 0u, 0u, 0u);
        for (int j = i; j < (H * B) / 8; j += 8192) h0[j] = z;
        if (i == 0) { g_arrive = 0u; g_cursor = 0u; }
        return;
    }
    int i = blockIdx.x * blockDim.x + threadIdx.x;
    {
        int r = hh_rows[i];
        int pos = atomicAdd(&g_cntHH[r], 1);
        g_hh_pair[g_hh_ptr[r] + pos] = make_int2(hh_cols[i], __float_as_int(hh_vals[i]));
    }
    if (i < NNZ_IH) {
        int r = ih_rows[i];
        int pos = atomicAdd(&g_cntIH[r], 1);
        g_ih_pair[g_ih_ptr[r] + pos] = make_int2(ih_cols[i], __float_as_int(ih_vals[i]));
    }
    if (i < NNZ_HO) {
        int r = ho_rows[i];
        int pos = atomicAdd(&g_cntHO[r], 1);
        g_ho_pair[g_ho_ptr[r] + pos] = make_int2(ho_cols[i], __float_as_int(ho_vals[i]));
    }
}

// ---------------- fp16 gather, LDG.128 flavor --------------------------------
// Layout: sub = lane>>2 (8 concurrent nnz per shuffle-step), bq = lane&3.
// Each lane loads uint4 = 8 halfs (batch bq*8..bq*8+7) of its sub's nnz row.
__device__ __forceinline__ void h8fma(float v, uint4 g, float4& lo, float4& hi) {
    float2 f0 = __half22float2(*reinterpret_cast<__half2*>(&g.x));
    float2 f1 = __half22float2(*reinterpret_cast<__half2*>(&g.y));
    float2 f2 = __half22float2(*reinterpret_cast<__half2*>(&g.z));
    float2 f3 = __half22float2(*reinterpret_cast<__half2*>(&g.w));
    lo.x += v * f0.x; lo.y += v * f0.y; lo.z += v * f1.x; lo.w += v * f1.y;
    hi.x += v * f2.x; hi.y += v * f2.y; hi.z += v * f3.x; hi.w += v * f3.y;
}

__device__ __forceinline__ void gather8h(const int2* __restrict__ pair,
                                         int k0, int e,
                                         const uint4* __restrict__ src4,
                                         int lane, int sub, int bq,
                                         float4& lo, float4& hi) {
    for (; k0 + 32 <= e; k0 += 32) {
        int2 p = __ldg(pair + k0 + lane);
#pragma unroll
        for (int j = 0; j < 4; j++) {
            int idx = (j << 3) + sub;
            int c = __shfl_sync(0xffffffffu, p.x, idx);
            float v = __int_as_float(__shfl_sync(0xffffffffu, p.y, idx));
            uint4 g = __ldg(src4 + c * 4 + bq);
            h8fma(v, g, lo, hi);
        }
    }
    int rem = e - k0;
    if (rem > 0) {
        int2 p = make_int2(0, 0);
        if (lane < rem) p = __ldg(pair + k0 + lane);
        int nsub = (rem + 7) >> 3;
        for (int j = 0; j < nsub; j++) {
            int idx = (j << 3) + sub;
            int c = __shfl_sync(0xffffffffu, p.x, idx);
            float v = __int_as_float(__shfl_sync(0xffffffffu, p.y, idx));
            if (idx >= rem) v = 0.f;
            uint4 g = __ldg(src4 + c * 4 + bq);
            h8fma(v, g, lo, hi);
        }
    }
}

// reduce across 8 sub groups (xor 4, 8, 16)
__device__ __forceinline__ void xreduce8(float4& lo, float4& hi) {
#pragma unroll
    for (int m = 4; m <= 16; m <<= 1) {
        lo.x += __shfl_xor_sync(0xffffffffu, lo.x, m);
        lo.y += __shfl_xor_sync(0xffffffffu, lo.y, m);
        lo.z += __shfl_xor_sync(0xffffffffu, lo.z, m);
        lo.w += __shfl_xor_sync(0xffffffffu, lo.w, m);
        hi.x += __shfl_xor_sync(0xffffffffu, hi.x, m);
        hi.y += __shfl_xor_sync(0xffffffffu, hi.y, m);
        hi.z += __shfl_xor_sync(0xffffffffu, hi.z, m);
        hi.w += __shfl_xor_sync(0xffffffffu, hi.w, m);
    }
}

__device__ __forceinline__ uint4 pack8h(float4 lo, float4 hi) {
    __half2 a = __floats2half2_rn(lo.x, lo.y);
    __half2 b = __floats2half2_rn(lo.z, lo.w);
    __half2 c = __floats2half2_rn(hi.x, hi.y);
    __half2 d = __floats2half2_rn(hi.z, hi.w);
    uint4 u;
    u.x = *reinterpret_cast<unsigned*>(&a);
    u.y = *reinterpret_cast<unsigned*>(&b);
    u.z = *reinterpret_cast<unsigned*>(&c);
    u.w = *reinterpret_cast<unsigned*>(&d);
    return u;
}

// ---------------- launch 4: fused ih + recurrence (persistent) --------------
__global__ void __launch_bounds__(RTHREADS, 1)
recur_kernel(const float* __restrict__ hhb) {
    __shared__ int bins[512];
    __shared__ int scn[512];
    int tid = threadIdx.x;
    int lane = tid & 31;
    int sub = lane >> 2, bq = lane & 3;
    int gw = blockIdx.x * (RTHREADS / 32) + (tid >> 5);
    unsigned target = 0;

    // ---- phase 0a: block 0 counting-sorts hh rows by length (ascending) ----
    if (blockIdx.x == 0) {
        if (tid < 512) bins[tid] = 0;
        __syncthreads();
        for (int r = tid; r < H; r += RTHREADS) {
            int c = g_hh_ptr[r + 1] - g_hh_ptr[r];
            atomicAdd(&bins[c < 511 ? c : 511], 1);
        }
        __syncthreads();
        if (tid < 512) scn[tid] = bins[tid];
        __syncthreads();
        for (int off = 1; off < 512; off <<= 1) {
            int v = (tid < 512 && tid >= off) ? scn[tid - off] : 0;
            __syncthreads();
            if (tid < 512) scn[tid] += v;
            __syncthreads();
        }
        if (tid < 512) bins[tid] = tid ? scn[tid - 1] : 0;
        __syncthreads();
        for (int r = tid; r < H; r += RTHREADS) {
            int c = g_hh_ptr[r + 1] - g_hh_ptr[r];
            int pos = atomicAdd(&bins[c < 511 ? c : 511], 1);
            g_order[pos] = r;
        }
    }

    // ---- phase 0b: ih (all t) via dynamic work queue ------------------------
    for (;;) {
        unsigned base;
        if (lane == 0) base = atomicAdd(&g_cursor, 32u);
        base = __shfl_sync(0xffffffffu, base, 0);
        if (base >= (unsigned)(T * H)) break;
#pragma unroll 1
        for (int q = 0; q < 32; q++) {
            unsigned wk = base + q;
            int r = wk & (H - 1);
            int t = wk >> 13;
            const uint4* __restrict__ xt4 = (const uint4*)(g_xTh + (size_t)t * IDIM * B);
            float4 lo = make_float4(0.f, 0.f, 0.f, 0.f);
            float4 hi = make_float4(0.f, 0.f, 0.f, 0.f);
            gather8h(g_ih_pair, g_ih_ptr[r], g_ih_ptr[r + 1], xt4, lane, sub, bq, lo, hi);
            xreduce8(lo, hi);
            if (lane < 4) {
                float bias = __ldg(hhb + r);
                lo.x += bias; lo.y += bias; lo.z += bias; lo.w += bias;
                hi.x += bias; hi.y += bias; hi.z += bias; hi.w += bias;
                float4* dst = (float4*)g_pre + (size_t)wk * 8 + lane * 2;
                dst[0] = lo;
                dst[1] = hi;
            }
        }
    }

    // ---- grid barrier (also publishes g_order) ------------------------------
    __threadfence();
    __syncthreads();
    target += RBLOCKS;
    if (tid == 0) {
        atomicAdd(&g_arrive, 1u);
        while (*(volatile unsigned*)&g_arrive < target) __nanosleep(64);
    }
    __syncthreads();

    // ---- balanced row assignment from sort ---------------------------------
    int r0, r1 = -1;
    if (gw < NSINGLE) {
        r0 = g_order[H - 1 - gw];                    // longest rows -> singles
    } else {
        int i = gw - NSINGLE;
        r0 = g_order[H - NSINGLE - 1 - i];           // long
        r1 = g_order[i];                             // paired with short
    }
    bool two = (r1 >= 0);
    int s0 = g_hh_ptr[r0], e0 = g_hh_ptr[r0 + 1];
    int s1 = 0, e1 = 0;
    if (two) { s1 = g_hh_ptr[r1]; e1 = g_hh_ptr[r1 + 1]; }

    // ---- T recurrent steps ---------------------------------------------------
    for (int t = 0; t < T; t++) {
        const uint4* __restrict__ hin4 = (const uint4*)g_hsH[t];
        uint4* __restrict__ hout4 = (uint4*)g_hsH[t + 1];
        float4 L0 = make_float4(0.f, 0.f, 0.f, 0.f), H0 = L0;
        float4 L1 = L0, H1 = L0;
        int k0 = s0, k1 = s1;

        if (two) {   // joint blocks: both rows' loads in flight
            int nj = min(e0 - k0, e1 - k1) >> 5;
            for (int i = 0; i < nj; i++) {
                int2 p0 = __ldg(g_hh_pair + k0 + lane);
                int2 p1 = __ldg(g_hh_pair + k1 + lane);
#pragma unroll
                for (int j = 0; j < 4; j++) {
                    int idx = (j << 3) + sub;
                    int c0 = __shfl_sync(0xffffffffu, p0.x, idx);
                    float v0 = __int_as_float(__shfl_sync(0xffffffffu, p0.y, idx));
                    int c1 = __shfl_sync(0xffffffffu, p1.x, idx);
                    float v1 = __int_as_float(__shfl_sync(0xffffffffu, p1.y, idx));
                    uint4 g0 = __ldg(hin4 + c0 * 4 + bq);
                    uint4 g1 = __ldg(hin4 + c1 * 4 + bq);
                    h8fma(v0, g0, L0, H0);
                    h8fma(v1, g1, L1, H1);
                }
                k0 += 32; k1 += 32;
            }
        }
        gather8h(g_hh_pair, k0, e0, hin4, lane, sub, bq, L0, H0);
        if (two) gather8h(g_hh_pair, k1, e1, hin4, lane, sub, bq, L1, H1);

        xreduce8(L0, H0);
        if (two) xreduce8(L1, H1);

        if (lane < 4) {
            const float4* pb = (const float4*)g_pre + ((size_t)t * H + r0) * 8 + lane * 2;
            float4 pa = __ldcg(pb);
            float4 pc = __ldcg(pb + 1);
            float4 lo, hi;
            lo.x = 1.0f / (1.0f + __expf(-(pa.x + L0.x)));
            lo.y = 1.0f / (1.0f + __expf(-(pa.y + L0.y)));
            lo.z = 1.0f / (1.0f + __expf(-(pa.z + L0.z)));
            lo.w = 1.0f / (1.0f + __expf(-(pa.w + L0.w)));
            hi.x = 1.0f / (1.0f + __expf(-(pc.x + H0.x)));
            hi.y = 1.0f / (1.0f + __expf(-(pc.y + H0.y)));
            hi.z = 1.0f / (1.0f + __expf(-(pc.z + H0.z)));
            hi.w = 1.0f / (1.0f + __expf(-(pc.w + H0.w)));
            hout4[r0 * 4 + lane] = pack8h(lo, hi);
        }
        if (two && lane < 4) {
            const float4* pb = (const float4*)g_pre + ((size_t)t * H + r1) * 8 + lane * 2;
            float4 pa = __ldcg(pb);
            float4 pc = __ldcg(pb + 1);
            float4 lo, hi;
            lo.x = 1.0f / (1.0f + __expf(-(pa.x + L1.x)));
            lo.y = 1.0f / (1.0f + __expf(-(pa.y + L1.y)));
            lo.z = 1.0f / (1.0f + __expf(-(pa.z + L1.z)));
            lo.w = 1.0f / (1.0f + __expf(-(pa.w + L1.w)));
            hi.x = 1.0f / (1.0f + __expf(-(pc.x + H1.x)));
            hi.y = 1.0f / (1.0f + __expf(-(pc.y + H1.y)));
            hi.z = 1.0f / (1.0f + __expf(-(pc.z + H1.z)));
            hi.w = 1.0f / (1.0f + __expf(-(pc.w + H1.w)));
            hout4[r1 * 4 + lane] = pack8h(lo, hi);
        }

        if (t < T - 1) {   // grid barrier
            __threadfence();
            __syncthreads();
            target += RBLOCKS;
            if (tid == 0) {
                atomicAdd(&g_arrive, 1u);
                while (*(volatile unsigned*)&g_arrive < target) __nanosleep(64);
            }
            __syncthreads();
        }
    }
}

// ---------------- launch 5: out = ho @ h_{t+1} (+ counter re-zero) ----------
#define HO_BLOCKS ((T * ODIM) / 8)
__global__ void ho_kernel(const float* __restrict__ hob) {
    if (blockIdx.x >= HO_BLOCKS) {
        int i = (blockIdx.x - HO_BLOCKS) * 256 + threadIdx.x;
        if (i < H) g_cntHH[i] = 0;
        if (i < H) g_cntIH[i] = 0;
        if (i < ODIM) g_cntHO[i] = 0;
        return;
    }
    int w = (blockIdx.x * 256 + threadIdx.x) >> 5;
    int lane = threadIdx.x & 31;
    int sub = lane >> 2, bq = lane & 3;
    int r = w & (ODIM - 1);
    int t = w >> 11;
    const uint4* __restrict__ h4 = (const uint4*)g_hsH[t + 1];
    float4 lo = make_float4(0.f, 0.f, 0.f, 0.f);
    float4 hi = make_float4(0.f, 0.f, 0.f, 0.f);
    gather8h(g_ho_pair, g_ho_ptr[r], g_ho_ptr[r + 1], h4, lane, sub, bq, lo, hi);
    xreduce8(lo, hi);
    if (lane < 4) {
        float bias = __ldg(hob + r);
        lo.x += bias; lo.y += bias; lo.z += bias; lo.w += bias;
        hi.x += bias; hi.y += bias; hi.z += bias; hi.w += bias;
        float4* dst = (float4*)g_outT + (size_t)w * 8 + lane * 2;
        dst[0] = lo;
        dst[1] = hi;
    }
}

// ---------------- launch 6: (T,O,B) -> (B,T,O) ------------------------------
__global__ void out_transpose_kernel(float* __restrict__ out) {
    __shared__ float tile[32][33];
    int t  = blockIdx.y;
    int o0 = blockIdx.x * 32;
    int tx = threadIdx.x, ty = threadIdx.y;
    tile[ty][tx] = g_outT[((size_t)t * ODIM + o0 + ty) * B + tx];
    __syncthreads();
    out[(size_t)ty * (T * ODIM) + (size_t)t * ODIM + o0 + tx] = tile[tx][ty];
}

// ---------------- launch ----------------
extern "C" void kernel_launch(void* const* d_in, const int* in_sizes, int n_in,
                              void* d_out, int out_size) {
    const float* x       = (const float*)d_in[0];
    const int*   hh_rows = (const int*)  d_in[1];
    const int*   hh_cols = (const int*)  d_in[2];
    const float* hh_vals = (const float*)d_in[3];
    const float* hh_bias = (const float*)d_in[4];
    const int*   ih_rows = (const int*)  d_in[5];
    const int*   ih_cols = (const int*)  d_in[6];
    const float* ih_vals = (const float*)d_in[7];
    const int*   ho_rows = (const int*)  d_in[8];
    const int*   ho_cols = (const int*)  d_in[9];
    const float* ho_vals = (const float*)d_in[10];
    const float* ho_bias = (const float*)d_in[11];
    float* out = (float*)d_out;

    hist_prep_kernel<<<HIST_BLOCKS + T * (IDIM / 32), 256>>>(hh_rows, ih_rows, ho_rows, x);
    scan_all_kernel<<<3, 1024>>>();
    scatter_all_kernel<<<HIST_BLOCKS + 32, 256>>>(hh_rows, hh_cols, hh_vals,
                                                  ih_rows, ih_cols, ih_vals,
                                                  ho_rows, ho_cols, ho_vals);
    recur_kernel<<<RBLOCKS, RTHREADS>>>(hh_bias);      // launch #4 -> profiled
    ho_kernel<<<HO_BLOCKS + 32, 256>>>(ho_bias);
    out_transpose_kernel<<<dim3(ODIM / 32, T), dim3(32, 32)>>>(out);
}

// round 8
// speedup vs baseline: 1.9817x; 1.0128x over previous
#include <cuda_runtime.h>
#include <cuda_fp16.h>

#define B 32
#define T 32
#define IDIM 8192
#define H 8192
#define ODIM 2048
#define NNZ_HH 1048576
#define NNZ_IH 524288
#define NNZ_HO 262144

#define RBLOCKS 148
#define RTHREADS 1024
#define RWARPS ((RBLOCKS * RTHREADS) / 32)   // 4736
#define NSINGLE (2 * RWARPS - H)             // 1280 warps carry one row

// ---------------- device scratch (static, zero-init at load) ----------------
__device__ __half g_xTh[(size_t)T * IDIM * B];    // (t, i, b) fp16
__device__ float  g_pre[(size_t)T * H * B];       // hh_bias + ih@x_t (fp32)
__device__ __half g_hsH[T + 1][H * B];            // h_0..h_T fp16
__device__ float  g_outT[(size_t)T * ODIM * B];   // (t, o, b)
__device__ int    g_cntHH[H];
__device__ int    g_cntIH[H];
__device__ int    g_cntHO[ODIM];
__device__ unsigned g_arrive;
__device__ unsigned g_cursor;
__device__ int    g_order[H];                     // hh rows sorted by nnz asc

__device__ int      g_hh_ptr[H + 1];
__device__ unsigned g_hh_pair[NNZ_HH];   // packed: col<<16 | fp16(val)
__device__ int      g_ih_ptr[H + 1];
__device__ unsigned g_ih_pair[NNZ_IH];
__device__ int      g_ho_ptr[ODIM + 1];
__device__ unsigned g_ho_pair[NNZ_HO];

// ---------------- launch 1: histograms + x transpose->fp16 ------------------
#define HIST_BLOCKS (NNZ_HH / 256)
__global__ void hist_prep_kernel(const int* __restrict__ hh_rows,
                                 const int* __restrict__ ih_rows,
                                 const int* __restrict__ ho_rows,
                                 const float* __restrict__ x) {
    if (blockIdx.x < HIST_BLOCKS) {
        int i = blockIdx.x * 256 + threadIdx.x;
        atomicAdd(&g_cntHH[hh_rows[i]], 1);
        if (i < NNZ_IH) atomicAdd(&g_cntIH[ih_rows[i]], 1);
        if (i < NNZ_HO) atomicAdd(&g_cntHO[ho_rows[i]], 1);
        return;
    }
    __shared__ float tile[32][33];
    int bi = blockIdx.x - HIST_BLOCKS;
    int t  = bi >> 8;
    int i0 = (bi & 255) << 5;
    int tx = threadIdx.x & 31;
    int ty = threadIdx.x >> 5;
    for (int bb = ty; bb < 32; bb += 8)
        tile[bb][tx] = x[(size_t)bb * T * IDIM + (size_t)t * IDIM + i0 + tx];
    __syncthreads();
    for (int ii = ty; ii < 32; ii += 8)
        g_xTh[(size_t)t * IDIM * B + (size_t)(i0 + ii) * B + tx] = __float2half(tile[tx][ii]);
}

// ---------------- launch 2: scan cnt -> ptr, re-zero cnt --------------------
__global__ void scan_all_kernel() {
    __shared__ int s[1024];
    int* cnt; int* ptr; int n;
    if (blockIdx.x == 0)      { cnt = g_cntHH; ptr = g_hh_ptr; n = H; }
    else if (blockIdx.x == 1) { cnt = g_cntIH; ptr = g_ih_ptr; n = H; }
    else                      { cnt = g_cntHO; ptr = g_ho_ptr; n = ODIM; }
    int tid = threadIdx.x;
    int per = (n + 1023) >> 10;
    int base = tid * per;
    int local[8];
    int sum = 0;
    for (int j = 0; j < per; j++) {
        int v = (base + j < n) ? cnt[base + j] : 0;
        local[j] = sum;
        sum += v;
    }
    s[tid] = sum;
    __syncthreads();
    for (int off = 1; off < 1024; off <<= 1) {
        int v = (tid >= off) ? s[tid - off] : 0;
        __syncthreads();
        s[tid] += v;
        __syncthreads();
    }
    int excl = tid ? s[tid - 1] : 0;
    for (int j = 0; j < per; j++)
        if (base + j < n) ptr[base + j] = excl + local[j];
    if (tid == 1023) ptr[n] = s[1023];
    __syncthreads();
    for (int j = 0; j < per; j++)
        if (base + j < n) cnt[base + j] = 0;
}

// ---------------- launch 3: scatter COO -> packed CSR + resets ---------------
__device__ __forceinline__ unsigned pack_pair(int col, float val) {
    __half hv = __float2half_rn(val);
    return ((unsigned)col << 16) | (unsigned)__half_as_ushort(hv);
}

__global__ void scatter_all_kernel(const int* __restrict__ hh_rows,
                                   const int* __restrict__ hh_cols,
                                   const float* __restrict__ hh_vals,
                                   const int* __restrict__ ih_rows,
                                   const int* __restrict__ ih_cols,
                                   const float* __restrict__ ih_vals,
                                   const int* __restrict__ ho_rows,
                                   const int* __restrict__ ho_cols,
                                   const float* __restrict__ ho_vals) {
    if (blockIdx.x >= HIST_BLOCKS) {   // 32 aux blocks: zero h0 (fp16) + flags
        int i = (blockIdx.x - HIST_BLOCKS) * 256 + threadIdx.x;   // 0..8191
        uint4* h0 = (uint4*)g_hsH[0];
        uint4 z = make_uint4(0u, 0u, 0u, 0u);
        for (int j = i; j < (H * B) / 8; j += 8192) h0[j] = z;
        if (i == 0) { g_arrive = 0u; g_cursor = 0u; }
        return;
    }
    int i = blockIdx.x * blockDim.x + threadIdx.x;
    {
        int r = hh_rows[i];
        int pos = atomicAdd(&g_cntHH[r], 1);
        g_hh_pair[g_hh_ptr[r] + pos] = pack_pair(hh_cols[i], hh_vals[i]);
    }
    if (i < NNZ_IH) {
        int r = ih_rows[i];
        int pos = atomicAdd(&g_cntIH[r], 1);
        g_ih_pair[g_ih_ptr[r] + pos] = pack_pair(ih_cols[i], ih_vals[i]);
    }
    if (i < NNZ_HO) {
        int r = ho_rows[i];
        int pos = atomicAdd(&g_cntHO[r], 1);
        g_ho_pair[g_ho_ptr[r] + pos] = pack_pair(ho_cols[i], ho_vals[i]);
    }
}

// ---------------- fp16 gather core -------------------------------------------
// Layout: sub = lane>>2 (8 concurrent nnz per shuffle-step), bq = lane&3.
// Each lane loads uint4 = 8 halfs (batch bq*8..bq*8+7) of its sub's nnz row.
__device__ __forceinline__ void h8fma(float v, uint4 g, float4& lo, float4& hi) {
    float2 f0 = __half22float2(*reinterpret_cast<__half2*>(&g.x));
    float2 f1 = __half22float2(*reinterpret_cast<__half2*>(&g.y));
    float2 f2 = __half22float2(*reinterpret_cast<__half2*>(&g.z));
    float2 f3 = __half22float2(*reinterpret_cast<__half2*>(&g.w));
    lo.x += v * f0.x; lo.y += v * f0.y; lo.z += v * f1.x; lo.w += v * f1.y;
    hi.x += v * f2.x; hi.y += v * f2.y; hi.z += v * f3.x; hi.w += v * f3.y;
}

__device__ __forceinline__ void unpack_pair(unsigned u, int& c, float& v) {
    c = (int)(u >> 16);
    v = __half2float(__ushort_as_half((unsigned short)(u & 0xffffu)));
}

// pipelined gather over [k0, e): prefetches next pair block while computing
__device__ __forceinline__ void gather8h(const unsigned* __restrict__ pair,
                                         int k0, int e,
                                         const uint4* __restrict__ src4,
                                         int lane, int sub, int bq,
                                         float4& lo, float4& hi) {
    int nb = (e - k0) >> 5;
    if (nb > 0) {
        unsigned p = __ldg(pair + k0 + lane);
        for (int i = 0; i < nb; i++) {
            unsigned cur = p;
            if (i + 1 < nb) p = __ldg(pair + k0 + (i + 1) * 32 + lane);
#pragma unroll
            for (int j = 0; j < 4; j++) {
                int idx = (j << 3) + sub;
                unsigned u = __shfl_sync(0xffffffffu, cur, idx);
                int c; float v;
                unpack_pair(u, c, v);
                uint4 g = __ldg(src4 + c * 4 + bq);
                h8fma(v, g, lo, hi);
            }
        }
        k0 += nb * 32;
    }
    int rem = e - k0;
    if (rem > 0) {
        unsigned p = 0u;
        if (lane < rem) p = __ldg(pair + k0 + lane);
        int nsub = (rem + 7) >> 3;
        for (int j = 0; j < nsub; j++) {
            int idx = (j << 3) + sub;
            unsigned u = __shfl_sync(0xffffffffu, p, idx);
            int c; float v;
            unpack_pair(u, c, v);
            if (idx >= rem) v = 0.f;
            uint4 g = __ldg(src4 + c * 4 + bq);
            h8fma(v, g, lo, hi);
        }
    }
}

// reduce across 8 sub groups (xor 4, 8, 16)
__device__ __forceinline__ void xreduce8(float4& lo, float4& hi) {
#pragma unroll
    for (int m = 4; m <= 16; m <<= 1) {
        lo.x += __shfl_xor_sync(0xffffffffu, lo.x, m);
        lo.y += __shfl_xor_sync(0xffffffffu, lo.y, m);
        lo.z += __shfl_xor_sync(0xffffffffu, lo.z, m);
        lo.w += __shfl_xor_sync(0xffffffffu, lo.w, m);
        hi.x += __shfl_xor_sync(0xffffffffu, hi.x, m);
        hi.y += __shfl_xor_sync(0xffffffffu, hi.y, m);
        hi.z += __shfl_xor_sync(0xffffffffu, hi.z, m);
        hi.w += __shfl_xor_sync(0xffffffffu, hi.w, m);
    }
}

__device__ __forceinline__ uint4 pack8h(float4 lo, float4 hi) {
    __half2 a = __floats2half2_rn(lo.x, lo.y);
    __half2 b = __floats2half2_rn(lo.z, lo.w);
    __half2 c = __floats2half2_rn(hi.x, hi.y);
    __half2 d = __floats2half2_rn(hi.z, hi.w);
    uint4 u;
    u.x = *reinterpret_cast<unsigned*>(&a);
    u.y = *reinterpret_cast<unsigned*>(&b);
    u.z = *reinterpret_cast<unsigned*>(&c);
    u.w = *reinterpret_cast<unsigned*>(&d);
    return u;
}

// ---------------- launch 4: fused ih + recurrence (persistent) --------------
__global__ void __launch_bounds__(RTHREADS, 1)
recur_kernel(const float* __restrict__ hhb) {
    __shared__ int bins[512];
    __shared__ int scn[512];
    int tid = threadIdx.x;
    int lane = tid & 31;
    int sub = lane >> 2, bq = lane & 3;
    int gw = blockIdx.x * (RTHREADS / 32) + (tid >> 5);
    unsigned target = 0;

    // ---- phase 0a: block 0 counting-sorts hh rows by length (ascending) ----
    if (blockIdx.x == 0) {
        if (tid < 512) bins[tid] = 0;
        __syncthreads();
        for (int r = tid; r < H; r += RTHREADS) {
            int c = g_hh_ptr[r + 1] - g_hh_ptr[r];
            atomicAdd(&bins[c < 511 ? c : 511], 1);
        }
        __syncthreads();
        if (tid < 512) scn[tid] = bins[tid];
        __syncthreads();
        for (int off = 1; off < 512; off <<= 1) {
            int v = (tid < 512 && tid >= off) ? scn[tid - off] : 0;
            __syncthreads();
            if (tid < 512) scn[tid] += v;
            __syncthreads();
        }
        if (tid < 512) bins[tid] = tid ? scn[tid - 1] : 0;
        __syncthreads();
        for (int r = tid; r < H; r += RTHREADS) {
            int c = g_hh_ptr[r + 1] - g_hh_ptr[r];
            int pos = atomicAdd(&bins[c < 511 ? c : 511], 1);
            g_order[pos] = r;
        }
    }

    // ---- phase 0b: ih (all t) via dynamic work queue ------------------------
    for (;;) {
        unsigned base;
        if (lane == 0) base = atomicAdd(&g_cursor, 32u);
        base = __shfl_sync(0xffffffffu, base, 0);
        if (base >= (unsigned)(T * H)) break;
#pragma unroll 1
        for (int q = 0; q < 32; q++) {
            unsigned wk = base + q;
            int r = wk & (H - 1);
            int t = wk >> 13;
            const uint4* __restrict__ xt4 = (const uint4*)(g_xTh + (size_t)t * IDIM * B);
            float4 lo = make_float4(0.f, 0.f, 0.f, 0.f);
            float4 hi = make_float4(0.f, 0.f, 0.f, 0.f);
            gather8h(g_ih_pair, g_ih_ptr[r], g_ih_ptr[r + 1], xt4, lane, sub, bq, lo, hi);
            xreduce8(lo, hi);
            if (lane < 4) {
                float bias = __ldg(hhb + r);
                lo.x += bias; lo.y += bias; lo.z += bias; lo.w += bias;
                hi.x += bias; hi.y += bias; hi.z += bias; hi.w += bias;
                float4* dst = (float4*)g_pre + (size_t)wk * 8 + lane * 2;
                dst[0] = lo;
                dst[1] = hi;
            }
        }
    }

    // ---- grid barrier (also publishes g_order) ------------------------------
    __threadfence();
    __syncthreads();
    target += RBLOCKS;
    if (tid == 0) {
        atomicAdd(&g_arrive, 1u);
        while (*(volatile unsigned*)&g_arrive < target) __nanosleep(64);
    }
    __syncthreads();

    // ---- balanced row assignment from sort ---------------------------------
    int r0, r1 = -1;
    if (gw < NSINGLE) {
        r0 = g_order[H - 1 - gw];                    // longest rows -> singles
    } else {
        int i = gw - NSINGLE;
        r0 = g_order[H - NSINGLE - 1 - i];           // long
        r1 = g_order[i];                             // paired with short
    }
    bool two = (r1 >= 0);
    int s0 = g_hh_ptr[r0], e0 = g_hh_ptr[r0 + 1];
    int s1 = 0, e1 = 0;
    if (two) { s1 = g_hh_ptr[r1]; e1 = g_hh_ptr[r1 + 1]; }

    // ---- T recurrent steps ---------------------------------------------------
    for (int t = 0; t < T; t++) {
        const uint4* __restrict__ hin4 = (const uint4*)g_hsH[t];
        uint4* __restrict__ hout4 = (uint4*)g_hsH[t + 1];
        float4 L0 = make_float4(0.f, 0.f, 0.f, 0.f), H0 = L0;
        float4 L1 = L0, H1 = L0;
        int k0 = s0, k1 = s1;

        if (two) {   // joint pipelined blocks: both rows' loads in flight
            int nj = min(e0 - k0, e1 - k1) >> 5;
            if (nj > 0) {
                unsigned p0 = __ldg(g_hh_pair + k0 + lane);
                unsigned p1 = __ldg(g_hh_pair + k1 + lane);
                for (int i = 0; i < nj; i++) {
                    unsigned c0w = p0, c1w = p1;
                    if (i + 1 < nj) {
                        p0 = __ldg(g_hh_pair + k0 + 32 + lane);
                        p1 = __ldg(g_hh_pair + k1 + 32 + lane);
                    }
#pragma unroll
                    for (int j = 0; j < 4; j++) {
                        int idx = (j << 3) + sub;
                        unsigned u0 = __shfl_sync(0xffffffffu, c0w, idx);
                        unsigned u1 = __shfl_sync(0xffffffffu, c1w, idx);
                        int c0i, c1i; float v0, v1;
                        unpack_pair(u0, c0i, v0);
                        unpack_pair(u1, c1i, v1);
                        uint4 g0 = __ldg(hin4 + c0i * 4 + bq);
                        uint4 g1 = __ldg(hin4 + c1i * 4 + bq);
                        h8fma(v0, g0, L0, H0);
                        h8fma(v1, g1, L1, H1);
                    }
                    k0 += 32; k1 += 32;
                }
            }
        }
        gather8h(g_hh_pair, k0, e0, hin4, lane, sub, bq, L0, H0);
        if (two) gather8h(g_hh_pair, k1, e1, hin4, lane, sub, bq, L1, H1);

        xreduce8(L0, H0);
        if (two) xreduce8(L1, H1);

        if (lane < 4) {
            const float4* pb = (const float4*)g_pre + ((size_t)t * H + r0) * 8 + lane * 2;
            float4 pa = __ldcg(pb);
            float4 pc = __ldcg(pb + 1);
            float4 lo, hi;
            lo.x = 1.0f / (1.0f + __expf(-(pa.x + L0.x)));
            lo.y = 1.0f / (1.0f + __expf(-(pa.y + L0.y)));
            lo.z = 1.0f / (1.0f + __expf(-(pa.z + L0.z)));
            lo.w = 1.0f / (1.0f + __expf(-(pa.w + L0.w)));
            hi.x = 1.0f / (1.0f + __expf(-(pc.x + H0.x)));
            hi.y = 1.0f / (1.0f + __expf(-(pc.y + H0.y)));
            hi.z = 1.0f / (1.0f + __expf(-(pc.z + H0.z)));
            hi.w = 1.0f / (1.0f + __expf(-(pc.w + H0.w)));
            hout4[r0 * 4 + lane] = pack8h(lo, hi);
        }
        if (two && lane < 4) {
            const float4* pb = (const float4*)g_pre + ((size_t)t * H + r1) * 8 + lane * 2;
            float4 pa = __ldcg(pb);
            float4 pc = __ldcg(pb + 1);
            float4 lo, hi;
            lo.x = 1.0f / (1.0f + __expf(-(pa.x + L1.x)));
            lo.y = 1.0f / (1.0f + __expf(-(pa.y + L1.y)));
            lo.z = 1.0f / (1.0f + __expf(-(pa.z + L1.z)));
            lo.w = 1.0f / (1.0f + __expf(-(pa.w + L1.w)));
            hi.x = 1.0f / (1.0f + __expf(-(pc.x + H1.x)));
            hi.y = 1.0f / (1.0f + __expf(-(pc.y + H1.y)));
            hi.z = 1.0f / (1.0f + __expf(-(pc.z + H1.z)));
            hi.w = 1.0f / (1.0f + __expf(-(pc.w + H1.w)));
            hout4[r1 * 4 + lane] = pack8h(lo, hi);
        }

        if (t < T - 1) {   // grid barrier
            __threadfence();
            __syncthreads();
            target += RBLOCKS;
            if (tid == 0) {
                atomicAdd(&g_arrive, 1u);
                while (*(volatile unsigned*)&g_arrive < target) __nanosleep(64);
            }
            __syncthreads();
        }
    }
}

// ---------------- launch 5: out = ho @ h_{t+1} (+ counter re-zero) ----------
#define HO_BLOCKS ((T * ODIM) / 8)
__global__ void ho_kernel(const float* __restrict__ hob) {
    if (blockIdx.x >= HO_BLOCKS) {
        int i = (blockIdx.x - HO_BLOCKS) * 256 + threadIdx.x;
        if (i < H) g_cntHH[i] = 0;
        if (i < H) g_cntIH[i] = 0;
        if (i < ODIM) g_cntHO[i] = 0;
        return;
    }
    int w = (blockIdx.x * 256 + threadIdx.x) >> 5;
    int lane = threadIdx.x & 31;
    int sub = lane >> 2, bq = lane & 3;
    int r = w & (ODIM - 1);
    int t = w >> 11;
    const uint4* __restrict__ h4 = (const uint4*)g_hsH[t + 1];
    float4 lo = make_float4(0.f, 0.f, 0.f, 0.f);
    float4 hi = make_float4(0.f, 0.f, 0.f, 0.f);
    gather8h(g_ho_pair, g_ho_ptr[r], g_ho_ptr[r + 1], h4, lane, sub, bq, lo, hi);
    xreduce8(lo, hi);
    if (lane < 4) {
        float bias = __ldg(hob + r);
        lo.x += bias; lo.y += bias; lo.z += bias; lo.w += bias;
        hi.x += bias; hi.y += bias; hi.z += bias; hi.w += bias;
        float4* dst = (float4*)g_outT + (size_t)w * 8 + lane * 2;
        dst[0] = lo;
        dst[1] = hi;
    }
}

// ---------------- launch 6: (T,O,B) -> (B,T,O) ------------------------------
__global__ void out_transpose_kernel(float* __restrict__ out) {
    __shared__ float tile[32][33];
    int t  = blockIdx.y;
    int o0 = blockIdx.x * 32;
    int tx = threadIdx.x, ty = threadIdx.y;
    tile[ty][tx] = g_outT[((size_t)t * ODIM + o0 + ty) * B + tx];
    __syncthreads();
    out[(size_t)ty * (T * ODIM) + (size_t)t * ODIM + o0 + tx] = tile[tx][ty];
}

// ---------------- launch ----------------
extern "C" void kernel_launch(void* const* d_in, const int* in_sizes, int n_in,
                              void* d_out, int out_size) {
    const float* x       = (const float*)d_in[0];
    const int*   hh_rows = (const int*)  d_in[1];
    const int*   hh_cols = (const int*)  d_in[2];
    const float* hh_vals = (const float*)d_in[3];
    const float* hh_bias = (const float*)d_in[4];
    const int*   ih_rows = (const int*)  d_in[5];
    const int*   ih_cols = (const int*)  d_in[6];
    const float* ih_vals = (const float*)d_in[7];
    const int*   ho_rows = (const int*)  d_in[8];
    const int*   ho_cols = (const int*)  d_in[9];
    const float* ho_vals = (const float*)d_in[10];
    const float* ho_bias = (const float*)d_in[11];
    float* out = (float*)d_out;

    hist_prep_kernel<<<HIST_BLOCKS + T * (IDIM / 32), 256>>>(hh_rows, ih_rows, ho_rows, x);
    scan_all_kernel<<<3, 1024>>>();
    scatter_all_kernel<<<HIST_BLOCKS + 32, 256>>>(hh_rows, hh_cols, hh_vals,
                                                  ih_rows, ih_cols, ih_vals,
                                                  ho_rows, ho_cols, ho_vals);
    recur_kernel<<<RBLOCKS, RTHREADS>>>(hh_bias);      // launch #4 -> profiled
    ho_kernel<<<HO_BLOCKS + 32, 256>>>(ho_bias);
    out_transpose_kernel<<<dim3(ODIM / 32, T), dim3(32, 32)>>>(out);
}